// round 4
// baseline (speedup 1.0000x reference)
#include <cuda_runtime.h>
#include <cuda_bf16.h>
#include <math.h>

// Problem constants (fixed by setup_inputs)
#define PB 2
#define PT 2048
#define PC 2048
#define PH 16
#define PD 128
#define PM (PB*PT)        // 4096 rows of x
#define PHD (PH*PD)       // 2048

// ---------------- scratch (device globals; no allocs allowed) ----------------
__device__ float g_q[PB*PT*PH*PD];
__device__ float g_k[PB*PT*PH*PD];
__device__ float g_v[PB*PT*PH*PD];
__device__ float g_y[PB*PT*PH*PD];
__device__ float g_lf[PB*PH*PT];
__device__ float g_cf[PB*PH*PT];

// ---------------- tf32 tensor-core GEMM: C[M,N] = A[M,K] @ B[K,N] ------------
// 128x128x32 CTA tile, 8 warps (4 along M x 2 along N), warp tile 32x64,
// mma.sync.m16n8k8 tf32, cp.async double-buffered smem.
#define ASTRIDE 36      // 128 rows x 36 (pad 4): frag reads conflict-free
#define BSTRIDE 136     // 32 rows x 136 (pad 8): frag reads conflict-free
#define ASZ (128*ASTRIDE)
#define BSZ (32*BSTRIDE)
#define TG_SMEM ((2*ASZ + 2*BSZ)*4)   // 71680 bytes

__device__ __forceinline__ unsigned f2tf(float f) {
    unsigned u;
    asm("cvt.rna.tf32.f32 %0, %1;" : "=r"(u) : "f"(f));
    return u;
}

__device__ __forceinline__ void cp16(void* smem_dst, const void* gsrc) {
    unsigned s = (unsigned)__cvta_generic_to_shared(smem_dst);
    asm volatile("cp.async.cg.shared.global [%0], [%1], 16;" :: "r"(s), "l"(gsrc));
}

__global__ __launch_bounds__(256) void tgemm(const float* __restrict__ A,
                                             const float* __restrict__ B,
                                             float* __restrict__ C,
                                             int M, int N, int K)
{
    extern __shared__ float sm[];
    float* As = sm;              // 2 stages of ASZ
    float* Bs = sm + 2 * ASZ;    // 2 stages of BSZ

    const int tid = threadIdx.x;
    const int bm = blockIdx.y * 128, bn = blockIdx.x * 128;
    const int lane = tid & 31, warp = tid >> 5;
    const int wm = (warp & 3) * 32;    // warp offset along M
    const int wn = (warp >> 2) * 64;   // warp offset along N
    const int g = lane >> 2, tg = lane & 3;

    float acc[2][8][4];
#pragma unroll
    for (int mt = 0; mt < 2; mt++)
#pragma unroll
        for (int nt = 0; nt < 8; nt++)
#pragma unroll
            for (int i = 0; i < 4; i++) acc[mt][nt][i] = 0.f;

    // global->smem load mapping (4 float4 per thread for each of A, B)
    const int arow = tid >> 3, ac = (tid & 7) * 4;   // A: rows arow+32i, cols ac..ac+3
    const int brow = tid >> 5, bc = (tid & 31) * 4;  // B: rows brow+8i,  cols bc..bc+3
    const float* Ag = A + (size_t)(bm + arow) * K + ac;
    const float* Bg = B + (size_t)brow * N + bn + bc;

    const int nT = K / 32;

    // prologue: stage 0
    {
#pragma unroll
        for (int i = 0; i < 4; i++)
            cp16(&As[(arow + 32 * i) * ASTRIDE + ac], Ag + (size_t)(32 * i) * K);
#pragma unroll
        for (int i = 0; i < 4; i++)
            cp16(&Bs[(brow + 8 * i) * BSTRIDE + bc], Bg + (size_t)(8 * i) * N);
        asm volatile("cp.async.commit_group;");
    }

    for (int t = 0; t < nT; t++) {
        if (t + 1 < nT) {
            float* Ad = As + ((t + 1) & 1) * ASZ;
            float* Bd = Bs + ((t + 1) & 1) * BSZ;
            const float* Ags = Ag + (t + 1) * 32;
            const float* Bgs = Bg + (size_t)(t + 1) * 32 * N;
#pragma unroll
            for (int i = 0; i < 4; i++)
                cp16(&Ad[(arow + 32 * i) * ASTRIDE + ac], Ags + (size_t)(32 * i) * K);
#pragma unroll
            for (int i = 0; i < 4; i++)
                cp16(&Bd[(brow + 8 * i) * BSTRIDE + bc], Bgs + (size_t)(8 * i) * N);
            asm volatile("cp.async.commit_group;");
            asm volatile("cp.async.wait_group 1;");
        } else {
            asm volatile("cp.async.wait_group 0;");
        }
        __syncthreads();

        const float* Ac = As + (t & 1) * ASZ;
        const float* Bc = Bs + (t & 1) * BSZ;

#pragma unroll
        for (int kk = 0; kk < 32; kk += 8) {
            unsigned af[2][4];
#pragma unroll
            for (int mt = 0; mt < 2; mt++) {
                const int r0 = wm + mt * 16 + g;
                af[mt][0] = f2tf(Ac[(r0)     * ASTRIDE + kk + tg]);
                af[mt][1] = f2tf(Ac[(r0 + 8) * ASTRIDE + kk + tg]);
                af[mt][2] = f2tf(Ac[(r0)     * ASTRIDE + kk + tg + 4]);
                af[mt][3] = f2tf(Ac[(r0 + 8) * ASTRIDE + kk + tg + 4]);
            }
#pragma unroll
            for (int nt = 0; nt < 8; nt++) {
                const int n = wn + nt * 8 + g;
                unsigned b0 = f2tf(Bc[(kk + tg)     * BSTRIDE + n]);
                unsigned b1 = f2tf(Bc[(kk + tg + 4) * BSTRIDE + n]);
#pragma unroll
                for (int mt = 0; mt < 2; mt++) {
                    asm volatile(
                        "mma.sync.aligned.m16n8k8.row.col.f32.tf32.tf32.f32 "
                        "{%0,%1,%2,%3}, {%4,%5,%6,%7}, {%8,%9}, {%0,%1,%2,%3};"
                        : "+f"(acc[mt][nt][0]), "+f"(acc[mt][nt][1]),
                          "+f"(acc[mt][nt][2]), "+f"(acc[mt][nt][3])
                        : "r"(af[mt][0]), "r"(af[mt][1]),
                          "r"(af[mt][2]), "r"(af[mt][3]),
                          "r"(b0), "r"(b1));
                }
            }
        }
        __syncthreads();
    }

    // epilogue: c0,c1 -> (row, 2tg..2tg+1); c2,c3 -> row+8
#pragma unroll
    for (int mt = 0; mt < 2; mt++) {
#pragma unroll
        for (int nt = 0; nt < 8; nt++) {
            const int row0 = bm + wm + mt * 16 + g;
            const int col = bn + wn + nt * 8 + 2 * tg;
            *(float2*)&C[(size_t)row0 * N + col] =
                make_float2(acc[mt][nt][0], acc[mt][nt][1]);
            *(float2*)&C[(size_t)(row0 + 8) * N + col] =
                make_float2(acc[mt][nt][2], acc[mt][nt][3]);
        }
    }
}

// ---------------- gate kernel: lam/logit/log_fgate per (b,t,h) ----------------
__global__ __launch_bounds__(256) void gate_kernel(const float* __restrict__ x,
                                                   const float* __restrict__ fw,
                                                   const float* __restrict__ fb,
                                                   const float* __restrict__ wl,
                                                   float* __restrict__ lf)
{
    __shared__ float xs[2048];
    __shared__ float red[256];
    __shared__ float dots[32];
    const int bt = blockIdx.x;
    const int tid = threadIdx.x;
    const float* xr = x + (size_t)bt * PC;
#pragma unroll
    for (int i = 0; i < 2; i++)
        *(float4*)&xs[(tid + 256 * i) * 4] = *(const float4*)&xr[(tid + 256 * i) * 4];
    __syncthreads();

    const int g = tid >> 5, o = tid & 31;
    const float* W = (o < 16) ? fw : wl;
    const int h = o & 15;
    float s = 0.f;
    for (int c = g; c < PC; c += 8) s += xs[c] * W[c * PH + h];
    red[tid] = s;
    __syncthreads();
    if (tid < 32) {
        float t = red[tid];
#pragma unroll
        for (int g2 = 1; g2 < 8; g2++) t += red[tid + 32 * g2];
        dots[tid] = t;
    }
    __syncthreads();
    if (tid < 16) {
        const int b = bt >> 11;       // /T
        const int t = bt & (PT - 1);
        float fdot = dots[tid] + fb[tid];
        float ldot = dots[16 + tid];
        float lam = ldot > 0.f ? ldot + 1.f : expf(ldot);  // elu(x)+1
        float logit = fdot * lam;
        float ls = (logit >= 0.f) ? -log1pf(expf(-logit))
                                  : (logit - log1pf(expf(logit)));
        lf[((size_t)(b * PH + tid)) * PT + t] = ls / (lam + 0.001f);
    }
}

// ---------------- cumsum over T per (b,h) ----------------
__global__ __launch_bounds__(256) void cumsum_kernel(const float* __restrict__ lf,
                                                     float* __restrict__ cf)
{
    __shared__ float tot[256];
    const int bh = blockIdx.x, tid = threadIdx.x;
    const float* in = lf + (size_t)bh * PT;
    float* out = cf + (size_t)bh * PT;
    float v[8];
    float r = 0.f;
#pragma unroll
    for (int j = 0; j < 8; j++) { r += in[tid * 8 + j]; v[j] = r; }
    tot[tid] = r;
    __syncthreads();
    for (int off = 1; off < 256; off <<= 1) {
        float t = 0.f;
        if (tid >= off) t = tot[tid - off];
        __syncthreads();
        if (tid >= off) tot[tid] += t;
        __syncthreads();
    }
    float base = tid ? tot[tid - 1] : 0.f;
#pragma unroll
    for (int j = 0; j < 8; j++) out[tid * 8 + j] = v[j] + base;
}

// ---------------- RoPE + RMSNorm, in place on [B,T,H,D] ----------------
__global__ __launch_bounds__(256) void rope_rms_kernel(float* __restrict__ data,
                                                       const float* __restrict__ cosp,
                                                       const float* __restrict__ sinp)
{
    const int wid = blockIdx.x * 8 + (threadIdx.x >> 5);   // (b,t,h) index
    const int lane = threadIdx.x & 31;
    const int t = (wid >> 4) & (PT - 1);
    float* row = data + (size_t)wid * PD;
    const int i0 = lane, i1 = lane + 32;
    float x1a = row[i0], x1b = row[i1];
    float x2a = row[i0 + 64], x2b = row[i1 + 64];
    float ca = cosp[t * 64 + i0], cb = cosp[t * 64 + i1];
    float sa = sinp[t * 64 + i0], sb = sinp[t * 64 + i1];
    float o0 = x1a * ca + x2a * sa;
    float o1 = x1b * cb + x2b * sb;
    float o2 = x2a * ca - x1a * sa;
    float o3 = x2b * cb - x1b * sb;
    float ss = o0 * o0 + o1 * o1 + o2 * o2 + o3 * o3;
#pragma unroll
    for (int off = 16; off > 0; off >>= 1) ss += __shfl_xor_sync(0xffffffffu, ss, off);
    float vv = ss * (1.f / 128.f) + 1.1920929e-07f;
    float inv = rsqrtf(vv);
    inv = inv * (1.5f - 0.5f * vv * inv * inv);  // Newton refine
    row[i0] = o0 * inv;
    row[i1] = o1 * inv;
    row[i0 + 64] = o2 * inv;
    row[i1 + 64] = o3 * inv;
}

// ---------------- windowed gated attention, flash-style, fp32 ----------------
// grid (T/64, H, B), 256 threads; smem: Q 32KB, K 32KB (xor-swizzled), V 32KB, P 16KB
__global__ __launch_bounds__(256) void attn_kernel(const float* __restrict__ Qg,
                                                   const float* __restrict__ Kg,
                                                   const float* __restrict__ Vg,
                                                   const float* __restrict__ cumF,
                                                   float* __restrict__ Y,
                                                   const int* __restrict__ winp)
{
    extern __shared__ float smA[];
    float* Qs = smA;                 // [64][128]
    float* Ks = Qs + 64 * 128;       // [64][128] xor-swizzled float4s
    float* Vs = Ks + 64 * 128;       // [64][128]
    float* Ps = Vs + 64 * 128;       // [64][64]

    const int tid = threadIdx.x;
    const int lane = tid & 31, w = tid >> 5;
    const int qt = blockIdx.x, h = blockIdx.y, b = blockIdx.z;
    const int q0 = qt * 64;
    const int win = *winp;
    const float sm_scale = 0.08838834764831845f;   // 1/sqrt(128)
    const float* cF = cumF + (size_t)(b * PH + h) * PT;

    // Load + pre-scale Q tile
    {
        const size_t base = ((size_t)(b * PT + q0) * PH + h) * PD;
#pragma unroll
        for (int i = 0; i < 8; i++) {
            int idx = tid + 256 * i;           // float4 index 0..2047
            int r = idx >> 5, d4 = idx & 31;
            float4 qv = *(const float4*)&Qg[base + (size_t)r * PHD + d4 * 4];
            qv.x *= sm_scale; qv.y *= sm_scale; qv.z *= sm_scale; qv.w *= sm_scale;
            *(float4*)&Qs[r * 128 + d4 * 4] = qv;
        }
    }
    float cfq[8];
#pragma unroll
    for (int r = 0; r < 8; r++) cfq[r] = cF[q0 + w * 8 + r];

    float m[8], l[8];
    float4 acc[8];
#pragma unroll
    for (int r = 0; r < 8; r++) {
        m[r] = -1e30f; l[r] = 0.f;
        acc[r] = make_float4(0.f, 0.f, 0.f, 0.f);
    }

    int lo = q0 - win + 1;
    int kt_min = lo > 0 ? (lo >> 6) : 0;

    for (int kt = qt; kt >= kt_min; --kt) {
        const int kb = kt * 64;
        __syncthreads();
        {
            const size_t base = ((size_t)(b * PT + kb) * PH + h) * PD;
#pragma unroll
            for (int i = 0; i < 8; i++) {
                int idx = tid + 256 * i;
                int r = idx >> 5, d4 = idx & 31;
                float4 kv = *(const float4*)&Kg[base + (size_t)r * PHD + d4 * 4];
                *(float4*)&Ks[r * 128 + ((d4 ^ (r & 31)) << 2)] = kv;
                float4 vv = *(const float4*)&Vg[base + (size_t)r * PHD + d4 * 4];
                *(float4*)&Vs[r * 128 + d4 * 4] = vv;
            }
        }
        __syncthreads();

        // S = Qs · Ks^T : warp w owns rows w*8..w*8+7; lane owns cols lane, lane+32
        float s0[8], s1[8];
#pragma unroll
        for (int r = 0; r < 8; r++) { s0[r] = 0.f; s1[r] = 0.f; }
        const float* K0row = &Ks[lane * 128];
        const float* K1row = &Ks[(lane + 32) * 128];
#pragma unroll 2
        for (int d4 = 0; d4 < 32; d4++) {
            float4 k0 = *(const float4*)&K0row[(d4 ^ lane) << 2];
            float4 k1 = *(const float4*)&K1row[(d4 ^ lane) << 2];
#pragma unroll
            for (int r = 0; r < 8; r++) {
                float4 qv = *(const float4*)&Qs[(w * 8 + r) * 128 + d4 * 4];
                s0[r] += qv.x * k0.x + qv.y * k0.y + qv.z * k0.z + qv.w * k0.w;
                s1[r] += qv.x * k1.x + qv.y * k1.y + qv.z * k1.z + qv.w * k1.w;
            }
        }

        // bias + mask + online softmax
        const float cfk0 = cF[kb + lane];
        const float cfk1 = cF[kb + lane + 32];
        const int j0 = kb + lane, j1 = j0 + 32;
#pragma unroll
        for (int r = 0; r < 8; r++) {
            const int qi = q0 + w * 8 + r;
            float v0 = (j0 <= qi && qi - j0 < win) ? s0[r] + cfq[r] - cfk0 : -1e30f;
            float v1 = (j1 <= qi && qi - j1 < win) ? s1[r] + cfq[r] - cfk1 : -1e30f;
            float mx = fmaxf(v0, v1);
#pragma unroll
            for (int off = 16; off > 0; off >>= 1)
                mx = fmaxf(mx, __shfl_xor_sync(0xffffffffu, mx, off));
            float mn = fmaxf(m[r], mx);
            float sc = expf(m[r] - mn);
            m[r] = mn;
            float p0 = expf(v0 - mn);
            float p1 = expf(v1 - mn);
            float rs = p0 + p1;
#pragma unroll
            for (int off = 16; off > 0; off >>= 1)
                rs += __shfl_xor_sync(0xffffffffu, rs, off);
            l[r] = l[r] * sc + rs;
            Ps[(w * 8 + r) * 64 + lane] = p0;
            Ps[(w * 8 + r) * 64 + lane + 32] = p1;
            acc[r].x *= sc; acc[r].y *= sc; acc[r].z *= sc; acc[r].w *= sc;
        }
        __syncwarp();

        // acc += P · V : lane owns d = lane*4..lane*4+3
#pragma unroll 2
        for (int k4 = 0; k4 < 64; k4 += 4) {
            float4 v0 = *(const float4*)&Vs[(k4 + 0) * 128 + lane * 4];
            float4 v1 = *(const float4*)&Vs[(k4 + 1) * 128 + lane * 4];
            float4 v2 = *(const float4*)&Vs[(k4 + 2) * 128 + lane * 4];
            float4 v3 = *(const float4*)&Vs[(k4 + 3) * 128 + lane * 4];
#pragma unroll
            for (int r = 0; r < 8; r++) {
                float4 p = *(const float4*)&Ps[(w * 8 + r) * 64 + k4];
                acc[r].x += p.x * v0.x + p.y * v1.x + p.z * v2.x + p.w * v3.x;
                acc[r].y += p.x * v0.y + p.y * v1.y + p.z * v2.y + p.w * v3.y;
                acc[r].z += p.x * v0.z + p.y * v1.z + p.z * v2.z + p.w * v3.z;
                acc[r].w += p.x * v0.w + p.y * v1.w + p.z * v2.w + p.w * v3.w;
            }
        }
        __syncwarp();
    }

    // epilogue: out = acc / l, write [B,T,H,D]
#pragma unroll
    for (int r = 0; r < 8; r++) {
        float inv = 1.f / l[r];
        size_t o = ((size_t)(b * PT + q0 + w * 8 + r) * PH + h) * PD + lane * 4;
        float4 ov = make_float4(acc[r].x * inv, acc[r].y * inv,
                                acc[r].z * inv, acc[r].w * inv);
        *(float4*)&Y[o] = ov;
    }
}

// ---------------- launch ----------------
extern "C" void kernel_launch(void* const* d_in, const int* in_sizes, int n_in,
                              void* d_out, int out_size)
{
    const float* x   = (const float*)d_in[0];
    const float* cosp= (const float*)d_in[1];
    const float* sinp= (const float*)d_in[2];
    const float* Wq  = (const float*)d_in[3];
    const float* Wk  = (const float*)d_in[4];
    const float* Wv  = (const float*)d_in[5];
    const float* Wo  = (const float*)d_in[6];
    const float* fw  = (const float*)d_in[7];
    const float* fb  = (const float*)d_in[8];
    const float* wl  = (const float*)d_in[9];
    const int*   win = (const int*)d_in[10];
    float* out = (float*)d_out;

    float *q, *k, *v, *y, *lf, *cf;
    cudaGetSymbolAddress((void**)&q, g_q);
    cudaGetSymbolAddress((void**)&k, g_k);
    cudaGetSymbolAddress((void**)&v, g_v);
    cudaGetSymbolAddress((void**)&y, g_y);
    cudaGetSymbolAddress((void**)&lf, g_lf);
    cudaGetSymbolAddress((void**)&cf, g_cf);

    cudaFuncSetAttribute(tgemm, cudaFuncAttributeMaxDynamicSharedMemorySize, TG_SMEM);

    dim3 gg(PHD / 128, PM / 128);                 // (16, 32)
    tgemm<<<gg, 256, TG_SMEM>>>(x, Wq, q, PM, PHD, PC);
    tgemm<<<gg, 256, TG_SMEM>>>(x, Wk, k, PM, PHD, PC);
    tgemm<<<gg, 256, TG_SMEM>>>(x, Wv, v, PM, PHD, PC);

    gate_kernel<<<PM, 256>>>(x, fw, fb, wl, lf);
    cumsum_kernel<<<PB * PH, 256>>>(lf, cf);

    rope_rms_kernel<<<(PB * PT * PH) / 8, 256>>>(q, cosp, sinp);
    rope_rms_kernel<<<(PB * PT * PH) / 8, 256>>>(k, cosp, sinp);

    const size_t attn_smem = (size_t)(3 * 64 * 128 + 64 * 64) * sizeof(float); // 114688
    cudaFuncSetAttribute(attn_kernel, cudaFuncAttributeMaxDynamicSharedMemorySize,
                         (int)attn_smem);
    dim3 ag(PT / 64, PH, PB);                     // (32, 16, 2)
    attn_kernel<<<ag, 256, attn_smem>>>(q, k, v, cf, y, win);

    tgemm<<<gg, 256, TG_SMEM>>>(y, Wo, out, PM, PC, PC);
}

// round 5
// speedup vs baseline: 1.5220x; 1.5220x over previous
#include <cuda_runtime.h>
#include <cuda_bf16.h>
#include <math.h>

// Problem constants (fixed by setup_inputs)
#define PB 2
#define PT 2048
#define PC 2048
#define PH 16
#define PD 128
#define PM (PB*PT)        // 4096 rows of x
#define PHD (PH*PD)       // 2048

// ---------------- scratch (device globals; no allocs allowed) ----------------
__device__ float g_q[PB*PT*PH*PD];
__device__ float g_k[PB*PT*PH*PD];
__device__ float g_v[PB*PT*PH*PD];
__device__ float g_y[PB*PT*PH*PD];
__device__ float g_lf[PB*PH*PT];
__device__ float g_cf[PB*PH*PT];

__device__ __forceinline__ unsigned f2tf(float f) {
    unsigned u;
    asm("cvt.rna.tf32.f32 %0, %1;" : "=r"(u) : "f"(f));
    return u;
}

__device__ __forceinline__ void cp16(void* smem_dst, const void* gsrc) {
    unsigned s = (unsigned)__cvta_generic_to_shared(smem_dst);
    asm volatile("cp.async.cg.shared.global [%0], [%1], 16;" :: "r"(s), "l"(gsrc));
}

__device__ __forceinline__ void mma_tf32(float* c, unsigned a0, unsigned a1,
                                         unsigned a2, unsigned a3,
                                         unsigned b0, unsigned b1) {
    asm volatile(
        "mma.sync.aligned.m16n8k8.row.col.f32.tf32.tf32.f32 "
        "{%0,%1,%2,%3}, {%4,%5,%6,%7}, {%8,%9}, {%0,%1,%2,%3};"
        : "+f"(c[0]), "+f"(c[1]), "+f"(c[2]), "+f"(c[3])
        : "r"(a0), "r"(a1), "r"(a2), "r"(a3), "r"(b0), "r"(b1));
}

// ---------------- tf32 tensor-core GEMM: C[M,N] = A[M,K] @ B[K,N] ------------
#define ASTRIDE 36
#define BSTRIDE 136
#define ASZ (128*ASTRIDE)
#define BSZ (32*BSTRIDE)
#define TG_SMEM ((2*ASZ + 2*BSZ)*4)   // 71680 bytes

__device__ __forceinline__ void tgemm_body(const float* __restrict__ A,
                                           const float* __restrict__ B,
                                           float* __restrict__ C,
                                           int M, int N, int K)
{
    extern __shared__ float sm[];
    float* As = sm;
    float* Bs = sm + 2 * ASZ;

    const int tid = threadIdx.x;
    const int bm = blockIdx.y * 128, bn = blockIdx.x * 128;
    const int lane = tid & 31, warp = tid >> 5;
    const int wm = (warp & 3) * 32;
    const int wn = (warp >> 2) * 64;
    const int g = lane >> 2, tg = lane & 3;

    float acc[2][8][4];
#pragma unroll
    for (int mt = 0; mt < 2; mt++)
#pragma unroll
        for (int nt = 0; nt < 8; nt++)
#pragma unroll
            for (int i = 0; i < 4; i++) acc[mt][nt][i] = 0.f;

    const int arow = tid >> 3, ac = (tid & 7) * 4;
    const int brow = tid >> 5, bc = (tid & 31) * 4;
    const float* Ag = A + (size_t)(bm + arow) * K + ac;
    const float* Bg = B + (size_t)brow * N + bn + bc;

    const int nT = K / 32;

    {
#pragma unroll
        for (int i = 0; i < 4; i++)
            cp16(&As[(arow + 32 * i) * ASTRIDE + ac], Ag + (size_t)(32 * i) * K);
#pragma unroll
        for (int i = 0; i < 4; i++)
            cp16(&Bs[(brow + 8 * i) * BSTRIDE + bc], Bg + (size_t)(8 * i) * N);
        asm volatile("cp.async.commit_group;");
    }

    for (int t = 0; t < nT; t++) {
        if (t + 1 < nT) {
            float* Ad = As + ((t + 1) & 1) * ASZ;
            float* Bd = Bs + ((t + 1) & 1) * BSZ;
            const float* Ags = Ag + (t + 1) * 32;
            const float* Bgs = Bg + (size_t)(t + 1) * 32 * N;
#pragma unroll
            for (int i = 0; i < 4; i++)
                cp16(&Ad[(arow + 32 * i) * ASTRIDE + ac], Ags + (size_t)(32 * i) * K);
#pragma unroll
            for (int i = 0; i < 4; i++)
                cp16(&Bd[(brow + 8 * i) * BSTRIDE + bc], Bgs + (size_t)(8 * i) * N);
            asm volatile("cp.async.commit_group;");
            asm volatile("cp.async.wait_group 1;");
        } else {
            asm volatile("cp.async.wait_group 0;");
        }
        __syncthreads();

        const float* Ac = As + (t & 1) * ASZ;
        const float* Bc = Bs + (t & 1) * BSZ;

#pragma unroll
        for (int kk = 0; kk < 32; kk += 8) {
            unsigned af[2][4];
#pragma unroll
            for (int mt = 0; mt < 2; mt++) {
                const int r0 = wm + mt * 16 + g;
                af[mt][0] = f2tf(Ac[(r0)     * ASTRIDE + kk + tg]);
                af[mt][1] = f2tf(Ac[(r0 + 8) * ASTRIDE + kk + tg]);
                af[mt][2] = f2tf(Ac[(r0)     * ASTRIDE + kk + tg + 4]);
                af[mt][3] = f2tf(Ac[(r0 + 8) * ASTRIDE + kk + tg + 4]);
            }
#pragma unroll
            for (int nt = 0; nt < 8; nt++) {
                const int n = wn + nt * 8 + g;
                unsigned b0 = f2tf(Bc[(kk + tg)     * BSTRIDE + n]);
                unsigned b1 = f2tf(Bc[(kk + tg + 4) * BSTRIDE + n]);
#pragma unroll
                for (int mt = 0; mt < 2; mt++)
                    mma_tf32(acc[mt][nt], af[mt][0], af[mt][1], af[mt][2], af[mt][3], b0, b1);
            }
        }
        __syncthreads();
    }

#pragma unroll
    for (int mt = 0; mt < 2; mt++) {
#pragma unroll
        for (int nt = 0; nt < 8; nt++) {
            const int row0 = bm + wm + mt * 16 + g;
            const int col = bn + wn + nt * 8 + 2 * tg;
            *(float2*)&C[(size_t)row0 * N + col] =
                make_float2(acc[mt][nt][0], acc[mt][nt][1]);
            *(float2*)&C[(size_t)(row0 + 8) * N + col] =
                make_float2(acc[mt][nt][2], acc[mt][nt][3]);
        }
    }
}

__global__ __launch_bounds__(256) void tgemm(const float* __restrict__ A,
                                             const float* __restrict__ B,
                                             float* __restrict__ C,
                                             int M, int N, int K)
{
    tgemm_body(A, B, C, M, N, K);
}

// merged QKV: grid.z selects weight/output
__global__ __launch_bounds__(256) void tgemm_qkv(const float* __restrict__ A,
                                                 const float* __restrict__ B0,
                                                 const float* __restrict__ B1,
                                                 const float* __restrict__ B2,
                                                 float* __restrict__ C0,
                                                 float* __restrict__ C1,
                                                 float* __restrict__ C2,
                                                 int M, int N, int K)
{
    const float* B = (blockIdx.z == 0) ? B0 : (blockIdx.z == 1) ? B1 : B2;
    float* C = (blockIdx.z == 0) ? C0 : (blockIdx.z == 1) ? C1 : C2;
    tgemm_body(A, B, C, M, N, K);
}

// ---------------- gate kernel: 4 rows/block, float4 W loads ----------------
__global__ __launch_bounds__(256) void gate_kernel(const float* __restrict__ x,
                                                   const float* __restrict__ fw,
                                                   const float* __restrict__ fb,
                                                   const float* __restrict__ wl,
                                                   float* __restrict__ lf)
{
    __shared__ float xs[4][2048];
    __shared__ float4 red4[8][8][4];     // [warp][grp][row]
    __shared__ float dots[4][32];
    const int bt0 = blockIdx.x * 4;
    const int tid = threadIdx.x;
    const int warp = tid >> 5, lane = tid & 31;
    const int grp = lane >> 2, koff = lane & 3;

    // load 4 x rows (4*2048 floats = 2048 float4, 8 per thread)
#pragma unroll
    for (int i = 0; i < 8; i++) {
        int idx = tid + 256 * i;                 // float4 index
        int row = idx >> 9, c4 = idx & 511;
        *(float4*)&xs[row][c4 * 4] =
            *(const float4*)&x[(size_t)(bt0 + row) * PC + c4 * 4];
    }
    __syncthreads();

    const float* W = (grp < 4) ? fw : wl;
    const int h4 = (grp & 3) * 4;
    float4 s[4];
#pragma unroll
    for (int r = 0; r < 4; r++) s[r] = make_float4(0.f, 0.f, 0.f, 0.f);

    for (int i = 0; i < 64; i++) {
        int c = koff + 4 * warp + 32 * i;
        float4 wv = *(const float4*)&W[c * PH + h4];
#pragma unroll
        for (int r = 0; r < 4; r++) {
            float xv = xs[r][c];
            s[r].x += xv * wv.x; s[r].y += xv * wv.y;
            s[r].z += xv * wv.z; s[r].w += xv * wv.w;
        }
    }
    // reduce over koff (quad)
#pragma unroll
    for (int off = 1; off < 4; off <<= 1) {
#pragma unroll
        for (int r = 0; r < 4; r++) {
            s[r].x += __shfl_xor_sync(0xffffffffu, s[r].x, off);
            s[r].y += __shfl_xor_sync(0xffffffffu, s[r].y, off);
            s[r].z += __shfl_xor_sync(0xffffffffu, s[r].z, off);
            s[r].w += __shfl_xor_sync(0xffffffffu, s[r].w, off);
        }
    }
    if (koff == 0) {
#pragma unroll
        for (int r = 0; r < 4; r++) red4[warp][grp][r] = s[r];
    }
    __syncthreads();
    if (tid < 128) {
        int row = tid >> 5, o = tid & 31;
        int gg = o >> 2, comp = o & 3;
        float t = 0.f;
#pragma unroll
        for (int w2 = 0; w2 < 8; w2++)
            t += ((const float*)&red4[w2][gg][row])[comp];
        dots[row][o] = t;
    }
    __syncthreads();
    if (tid < 64) {
        const int row = tid >> 4, hh = tid & 15;
        const int bt = bt0 + row;
        const int b = bt >> 11, t = bt & (PT - 1);
        float fdot = dots[row][hh] + fb[hh];
        float ldot = dots[row][16 + hh];
        float lam = ldot > 0.f ? ldot + 1.f : expf(ldot);
        float logit = fdot * lam;
        float ls = (logit >= 0.f) ? -log1pf(expf(-logit))
                                  : (logit - log1pf(expf(logit)));
        lf[((size_t)(b * PH + hh)) * PT + t] = ls / (lam + 0.001f);
    }
}

// ---------------- cumsum over T per (b,h) ----------------
__global__ __launch_bounds__(256) void cumsum_kernel(const float* __restrict__ lf,
                                                     float* __restrict__ cf)
{
    __shared__ float tot[256];
    const int bh = blockIdx.x, tid = threadIdx.x;
    const float* in = lf + (size_t)bh * PT;
    float* out = cf + (size_t)bh * PT;
    float v[8];
    float r = 0.f;
#pragma unroll
    for (int j = 0; j < 8; j++) { r += in[tid * 8 + j]; v[j] = r; }
    tot[tid] = r;
    __syncthreads();
    for (int off = 1; off < 256; off <<= 1) {
        float t = 0.f;
        if (tid >= off) t = tot[tid - off];
        __syncthreads();
        if (tid >= off) tot[tid] += t;
        __syncthreads();
    }
    float base = tid ? tot[tid - 1] : 0.f;
#pragma unroll
    for (int j = 0; j < 8; j++) out[tid * 8 + j] = v[j] + base;
}

// ---------------- RoPE + RMSNorm, in place on [B,T,H,D] ----------------
__global__ __launch_bounds__(256) void rope_rms_kernel(float* __restrict__ data,
                                                       const float* __restrict__ cosp,
                                                       const float* __restrict__ sinp)
{
    const int wid = blockIdx.x * 8 + (threadIdx.x >> 5);
    const int lane = threadIdx.x & 31;
    const int t = (wid >> 4) & (PT - 1);
    float* row = data + (size_t)wid * PD;
    const int i0 = lane, i1 = lane + 32;
    float x1a = row[i0], x1b = row[i1];
    float x2a = row[i0 + 64], x2b = row[i1 + 64];
    float ca = cosp[t * 64 + i0], cb = cosp[t * 64 + i1];
    float sa = sinp[t * 64 + i0], sb = sinp[t * 64 + i1];
    float o0 = x1a * ca + x2a * sa;
    float o1 = x1b * cb + x2b * sb;
    float o2 = x2a * ca - x1a * sa;
    float o3 = x2b * cb - x1b * sb;
    float ss = o0 * o0 + o1 * o1 + o2 * o2 + o3 * o3;
#pragma unroll
    for (int off = 16; off > 0; off >>= 1) ss += __shfl_xor_sync(0xffffffffu, ss, off);
    float vv = ss * (1.f / 128.f) + 1.1920929e-07f;
    float inv = rsqrtf(vv);
    inv = inv * (1.5f - 0.5f * vv * inv * inv);
    row[i0] = o0 * inv;
    row[i1] = o1 * inv;
    row[i0 + 64] = o2 * inv;
    row[i1 + 64] = o3 * inv;
}

// ---------------- windowed gated attention, tf32 tensor cores ----------------
// 128 queries x 64 keys per CTA, 8 warps x 16 rows, mma.m16n8k8.tf32.
#define QSTR 132
#define KSTR 132
#define VSTR 136
#define PSTR 68
#define AT_QS 0
#define AT_KS (AT_QS + 128*QSTR)
#define AT_VS (AT_KS + 64*KSTR)
#define AT_PS (AT_VS + 64*VSTR)
#define AT_CFK (AT_PS + 128*PSTR)
#define AT_SMEM ((AT_CFK + 64) * 4)     // 171520 bytes

__global__ __launch_bounds__(256) void attn_mma_kernel(const float* __restrict__ Qg,
                                                       const float* __restrict__ Kg,
                                                       const float* __restrict__ Vg,
                                                       const float* __restrict__ cumF,
                                                       float* __restrict__ Y,
                                                       const int* __restrict__ winp)
{
    extern __shared__ unsigned smu[];
    unsigned* Qs = smu + AT_QS;
    unsigned* Ks = smu + AT_KS;
    unsigned* Vs = smu + AT_VS;
    unsigned* Ps = smu + AT_PS;
    float* cfk = (float*)(smu + AT_CFK);

    const int tid = threadIdx.x;
    const int lane = tid & 31, warp = tid >> 5;
    const int g = lane >> 2, tg = lane & 3;
    const int wm = warp * 16;
    const int qt = blockIdx.x, h = blockIdx.y, b = blockIdx.z;
    const int q0 = qt * 128;
    const int win = *winp;
    const float sm_scale = 0.08838834764831845f;
    const float* cF = cumF + (size_t)(b * PH + h) * PT;

    // load Q tile (128x128), scale + tf32-convert
    {
        const size_t base = ((size_t)(b * PT + q0) * PH + h) * PD;
#pragma unroll
        for (int i = 0; i < 16; i++) {
            int idx = tid + 256 * i;           // float4 index
            int r = idx >> 5, d4 = idx & 31;
            float4 qv = *(const float4*)&Qg[base + (size_t)r * PHD + d4 * 4];
            uint4 u;
            u.x = f2tf(qv.x * sm_scale); u.y = f2tf(qv.y * sm_scale);
            u.z = f2tf(qv.z * sm_scale); u.w = f2tf(qv.w * sm_scale);
            *(uint4*)&Qs[r * QSTR + d4 * 4] = u;
        }
    }
    const int rowA = wm + g, rowB = wm + g + 8;
    const float cfqA = cF[q0 + rowA];
    const float cfqB = cF[q0 + rowB];
    const int qiA = q0 + rowA, qiB = q0 + rowB;

    float mA = -1e30f, mB = -1e30f, lA = 0.f, lB = 0.f;
    float acc[16][4];
#pragma unroll
    for (int nt = 0; nt < 16; nt++)
#pragma unroll
        for (int i = 0; i < 4; i++) acc[nt][i] = 0.f;

    const int kt_hi = (q0 + 127) >> 6;
    const int lo = q0 - win + 1;
    const int kt_min = lo > 0 ? (lo >> 6) : 0;

    for (int kt = kt_hi; kt >= kt_min; --kt) {
        const int kb = kt * 64;
        __syncthreads();
        {
            const size_t base = ((size_t)(b * PT + kb) * PH + h) * PD;
#pragma unroll
            for (int i = 0; i < 8; i++) {
                int idx = tid + 256 * i;
                int r = idx >> 5, d4 = idx & 31;
                float4 kv = *(const float4*)&Kg[base + (size_t)r * PHD + d4 * 4];
                uint4 uk;
                uk.x = f2tf(kv.x); uk.y = f2tf(kv.y); uk.z = f2tf(kv.z); uk.w = f2tf(kv.w);
                *(uint4*)&Ks[r * KSTR + d4 * 4] = uk;
                float4 vv = *(const float4*)&Vg[base + (size_t)r * PHD + d4 * 4];
                uint4 uv;
                uv.x = f2tf(vv.x); uv.y = f2tf(vv.y); uv.z = f2tf(vv.z); uv.w = f2tf(vv.w);
                *(uint4*)&Vs[r * VSTR + d4 * 4] = uv;
            }
            if (tid < 64) cfk[tid] = cF[kb + tid];
        }
        __syncthreads();

        // ---- S = Q K^T (warp rows wm..wm+15, cols 0..63) ----
        float sc_[8][4];
#pragma unroll
        for (int nt = 0; nt < 8; nt++)
#pragma unroll
            for (int i = 0; i < 4; i++) sc_[nt][i] = 0.f;

#pragma unroll
        for (int kk = 0; kk < 128; kk += 8) {
            unsigned a0 = Qs[rowA * QSTR + kk + tg];
            unsigned a1 = Qs[rowB * QSTR + kk + tg];
            unsigned a2 = Qs[rowA * QSTR + kk + tg + 4];
            unsigned a3 = Qs[rowB * QSTR + kk + tg + 4];
#pragma unroll
            for (int nt = 0; nt < 8; nt++) {
                const int n = nt * 8 + g;
                unsigned b0 = Ks[n * KSTR + kk + tg];
                unsigned b1 = Ks[n * KSTR + kk + tg + 4];
                mma_tf32(sc_[nt], a0, a1, a2, a3, b0, b1);
            }
        }

        // ---- bias + mask ----
#pragma unroll
        for (int nt = 0; nt < 8; nt++) {
            const int j0 = kb + nt * 8 + 2 * tg;
            const int j1 = j0 + 1;
            const float c0 = cfk[nt * 8 + 2 * tg];
            const float c1 = cfk[nt * 8 + 2 * tg + 1];
            sc_[nt][0] = (j0 <= qiA && qiA - j0 < win) ? sc_[nt][0] + cfqA - c0 : -1e30f;
            sc_[nt][1] = (j1 <= qiA && qiA - j1 < win) ? sc_[nt][1] + cfqA - c1 : -1e30f;
            sc_[nt][2] = (j0 <= qiB && qiB - j0 < win) ? sc_[nt][2] + cfqB - c0 : -1e30f;
            sc_[nt][3] = (j1 <= qiB && qiB - j1 < win) ? sc_[nt][3] + cfqB - c1 : -1e30f;
        }
        // ---- row max ----
        float mxA = -1e30f, mxB = -1e30f;
#pragma unroll
        for (int nt = 0; nt < 8; nt++) {
            mxA = fmaxf(mxA, fmaxf(sc_[nt][0], sc_[nt][1]));
            mxB = fmaxf(mxB, fmaxf(sc_[nt][2], sc_[nt][3]));
        }
#pragma unroll
        for (int off = 1; off < 4; off <<= 1) {
            mxA = fmaxf(mxA, __shfl_xor_sync(0xffffffffu, mxA, off));
            mxB = fmaxf(mxB, __shfl_xor_sync(0xffffffffu, mxB, off));
        }
        const float mnA = fmaxf(mA, mxA);
        const float mnB = fmaxf(mB, mxB);
        const float scaA = __expf(mA - mnA);
        const float scaB = __expf(mB - mnB);
        mA = mnA; mB = mnB;

        // ---- exp, row sum, write P (tf32) ----
        float rsA = 0.f, rsB = 0.f;
#pragma unroll
        for (int nt = 0; nt < 8; nt++) {
            float p0 = (sc_[nt][0] > -1e29f) ? __expf(sc_[nt][0] - mnA) : 0.f;
            float p1 = (sc_[nt][1] > -1e29f) ? __expf(sc_[nt][1] - mnA) : 0.f;
            float p2 = (sc_[nt][2] > -1e29f) ? __expf(sc_[nt][2] - mnB) : 0.f;
            float p3 = (sc_[nt][3] > -1e29f) ? __expf(sc_[nt][3] - mnB) : 0.f;
            rsA += p0 + p1;
            rsB += p2 + p3;
            uint2 uA = make_uint2(f2tf(p0), f2tf(p1));
            uint2 uB = make_uint2(f2tf(p2), f2tf(p3));
            *(uint2*)&Ps[rowA * PSTR + nt * 8 + 2 * tg] = uA;
            *(uint2*)&Ps[rowB * PSTR + nt * 8 + 2 * tg] = uB;
        }
#pragma unroll
        for (int off = 1; off < 4; off <<= 1) {
            rsA += __shfl_xor_sync(0xffffffffu, rsA, off);
            rsB += __shfl_xor_sync(0xffffffffu, rsB, off);
        }
        lA = lA * scaA + rsA;
        lB = lB * scaB + rsB;
#pragma unroll
        for (int nt = 0; nt < 16; nt++) {
            acc[nt][0] *= scaA; acc[nt][1] *= scaA;
            acc[nt][2] *= scaB; acc[nt][3] *= scaB;
        }
        __syncwarp();

        // ---- O += P V ----
#pragma unroll
        for (int kv = 0; kv < 64; kv += 8) {
            unsigned a0 = Ps[rowA * PSTR + kv + tg];
            unsigned a1 = Ps[rowB * PSTR + kv + tg];
            unsigned a2 = Ps[rowA * PSTR + kv + tg + 4];
            unsigned a3 = Ps[rowB * PSTR + kv + tg + 4];
#pragma unroll
            for (int nt = 0; nt < 16; nt++) {
                const int n = nt * 8 + g;
                unsigned b0 = Vs[(kv + tg) * VSTR + n];
                unsigned b1 = Vs[(kv + tg + 4) * VSTR + n];
                mma_tf32(acc[nt], a0, a1, a2, a3, b0, b1);
            }
        }
        __syncwarp();
    }

    // ---- epilogue ----
    const float invA = 1.f / lA;
    const float invB = 1.f / lB;
#pragma unroll
    for (int nt = 0; nt < 16; nt++) {
        const int col = nt * 8 + 2 * tg;
        size_t oA = ((size_t)(b * PT + q0 + rowA) * PH + h) * PD + col;
        size_t oB = ((size_t)(b * PT + q0 + rowB) * PH + h) * PD + col;
        *(float2*)&Y[oA] = make_float2(acc[nt][0] * invA, acc[nt][1] * invA);
        *(float2*)&Y[oB] = make_float2(acc[nt][2] * invB, acc[nt][3] * invB);
    }
}

// ---------------- launch ----------------
extern "C" void kernel_launch(void* const* d_in, const int* in_sizes, int n_in,
                              void* d_out, int out_size)
{
    const float* x   = (const float*)d_in[0];
    const float* cosp= (const float*)d_in[1];
    const float* sinp= (const float*)d_in[2];
    const float* Wq  = (const float*)d_in[3];
    const float* Wk  = (const float*)d_in[4];
    const float* Wv  = (const float*)d_in[5];
    const float* Wo  = (const float*)d_in[6];
    const float* fw  = (const float*)d_in[7];
    const float* fb  = (const float*)d_in[8];
    const float* wl  = (const float*)d_in[9];
    const int*   win = (const int*)d_in[10];
    float* out = (float*)d_out;

    float *q, *k, *v, *y, *lf, *cf;
    cudaGetSymbolAddress((void**)&q, g_q);
    cudaGetSymbolAddress((void**)&k, g_k);
    cudaGetSymbolAddress((void**)&v, g_v);
    cudaGetSymbolAddress((void**)&y, g_y);
    cudaGetSymbolAddress((void**)&lf, g_lf);
    cudaGetSymbolAddress((void**)&cf, g_cf);

    cudaFuncSetAttribute(tgemm, cudaFuncAttributeMaxDynamicSharedMemorySize, TG_SMEM);
    cudaFuncSetAttribute(tgemm_qkv, cudaFuncAttributeMaxDynamicSharedMemorySize, TG_SMEM);
    cudaFuncSetAttribute(attn_mma_kernel, cudaFuncAttributeMaxDynamicSharedMemorySize, AT_SMEM);

    dim3 gq(PHD / 128, PM / 128, 3);              // (16, 32, 3)
    tgemm_qkv<<<gq, 256, TG_SMEM>>>(x, Wq, Wk, Wv, q, k, v, PM, PHD, PC);

    gate_kernel<<<PM / 4, 256>>>(x, fw, fb, wl, lf);
    cumsum_kernel<<<PB * PH, 256>>>(lf, cf);

    rope_rms_kernel<<<(PB * PT * PH) / 8, 256>>>(q, cosp, sinp);
    rope_rms_kernel<<<(PB * PT * PH) / 8, 256>>>(k, cosp, sinp);

    dim3 ag(PT / 128, PH, PB);                    // (16, 16, 2)
    attn_mma_kernel<<<ag, 256, AT_SMEM>>>(q, k, v, cf, y, win);

    dim3 gg(PC / 128, PM / 128);                  // (16, 32)
    tgemm<<<gg, 256, TG_SMEM>>>(y, Wo, out, PM, PC, PC);
}

// round 6
// speedup vs baseline: 1.5373x; 1.0100x over previous
#include <cuda_runtime.h>
#include <cuda_bf16.h>
#include <math.h>

// Problem constants (fixed by setup_inputs)
#define PB 2
#define PT 2048
#define PC 2048
#define PH 16
#define PD 128
#define PM (PB*PT)        // 4096 rows of x
#define PHD (PH*PD)       // 2048

// ---------------- scratch (device globals; no allocs allowed) ----------------
__device__ float g_q[PB*PT*PH*PD];
__device__ float g_k[PB*PT*PH*PD];
__device__ float g_v[PB*PT*PH*PD];
__device__ float g_y[PB*PT*PH*PD];
__device__ float g_lf[PB*PH*PT];
__device__ float g_cf[PB*PH*PT];
// pre-converted (tf32-rounded) GEMM operands
__device__ float g_xt[PM*PC];
__device__ float g_wq[PC*PHD];
__device__ float g_wk[PC*PHD];
__device__ float g_wv[PC*PHD];
__device__ float g_wo[PC*PC];

__device__ __forceinline__ unsigned f2tf(float f) {
    unsigned u;
    asm("cvt.rna.tf32.f32 %0, %1;" : "=r"(u) : "f"(f));
    return u;
}

__device__ __forceinline__ void cp16(void* smem_dst, const void* gsrc) {
    unsigned s = (unsigned)__cvta_generic_to_shared(smem_dst);
    asm volatile("cp.async.cg.shared.global [%0], [%1], 16;" :: "r"(s), "l"(gsrc));
}

__device__ __forceinline__ void mma_tf32(float* c, unsigned a0, unsigned a1,
                                         unsigned a2, unsigned a3,
                                         unsigned b0, unsigned b1) {
    asm volatile(
        "mma.sync.aligned.m16n8k8.row.col.f32.tf32.tf32.f32 "
        "{%0,%1,%2,%3}, {%4,%5,%6,%7}, {%8,%9}, {%0,%1,%2,%3};"
        : "+f"(c[0]), "+f"(c[1]), "+f"(c[2]), "+f"(c[3])
        : "r"(a0), "r"(a1), "r"(a2), "r"(a3), "r"(b0), "r"(b1));
}

// ---------------- tf32 pre-conversion (elementwise, float4) ----------------
__global__ __launch_bounds__(256) void tf32_conv(const float* __restrict__ in,
                                                 float* __restrict__ out, int n4)
{
    int i = blockIdx.x * 256 + threadIdx.x;
    if (i < n4) {
        float4 v = ((const float4*)in)[i];
        uint4 u;
        u.x = f2tf(v.x); u.y = f2tf(v.y); u.z = f2tf(v.z); u.w = f2tf(v.w);
        ((uint4*)out)[i] = u;
    }
}

// ---------------- tf32 tensor-core GEMM: C[M,N] = A[M,K] @ B[K,N] ------------
// Inputs MUST be pre-rounded to tf32. 128x128x32 CTA tile, 8 warps,
// 3-stage cp.async pipeline, no CVT in the inner loop.
#define ASTRIDE 36
#define BSTRIDE 136
#define ASZ (128*ASTRIDE)
#define BSZ (32*BSTRIDE)
#define TG_SMEM ((3*ASZ + 3*BSZ)*4)   // 107520 bytes

__device__ __forceinline__ void tgemm_body(const float* __restrict__ A,
                                           const float* __restrict__ B,
                                           float* __restrict__ C,
                                           int M, int N, int K)
{
    extern __shared__ float sm[];
    float* As = sm;               // 3 stages of ASZ
    float* Bs = sm + 3 * ASZ;     // 3 stages of BSZ

    const int tid = threadIdx.x;
    const int bm = blockIdx.y * 128, bn = blockIdx.x * 128;
    const int lane = tid & 31, warp = tid >> 5;
    const int wm = (warp & 3) * 32;
    const int wn = (warp >> 2) * 64;
    const int g = lane >> 2, tg = lane & 3;

    float acc[2][8][4];
#pragma unroll
    for (int mt = 0; mt < 2; mt++)
#pragma unroll
        for (int nt = 0; nt < 8; nt++)
#pragma unroll
            for (int i = 0; i < 4; i++) acc[mt][nt][i] = 0.f;

    const int arow = tid >> 3, ac = (tid & 7) * 4;
    const int brow = tid >> 5, bc = (tid & 31) * 4;
    const float* Ag = A + (size_t)(bm + arow) * K + ac;
    const float* Bg = B + (size_t)brow * N + bn + bc;

    const int nT = K / 32;

#define LOAD_STAGE(T, S)                                                        \
    {                                                                           \
        float* Ad = As + (S) * ASZ;                                             \
        float* Bd = Bs + (S) * BSZ;                                             \
        const float* Ags = Ag + (T) * 32;                                       \
        const float* Bgs = Bg + (size_t)(T) * 32 * N;                           \
        _Pragma("unroll")                                                       \
        for (int i = 0; i < 4; i++)                                             \
            cp16(&Ad[(arow + 32 * i) * ASTRIDE + ac], Ags + (size_t)(32 * i) * K); \
        _Pragma("unroll")                                                       \
        for (int i = 0; i < 4; i++)                                             \
            cp16(&Bd[(brow + 8 * i) * BSTRIDE + bc], Bgs + (size_t)(8 * i) * N);\
        asm volatile("cp.async.commit_group;");                                 \
    }

    LOAD_STAGE(0, 0);
    LOAD_STAGE(1, 1);

    int sid = 0;      // t % 3
    int sid2 = 2;     // (t+2) % 3
    for (int t = 0; t < nT; t++) {
        if (t + 1 < nT) asm volatile("cp.async.wait_group 1;");
        else            asm volatile("cp.async.wait_group 0;");
        __syncthreads();
        if (t + 2 < nT) LOAD_STAGE(t + 2, sid2);

        const float* Ac = As + sid * ASZ;
        const float* Bc = Bs + sid * BSZ;

#pragma unroll
        for (int kk = 0; kk < 32; kk += 8) {
            unsigned af[2][4];
#pragma unroll
            for (int mt = 0; mt < 2; mt++) {
                const int r0 = wm + mt * 16 + g;
                af[mt][0] = __float_as_uint(Ac[(r0)     * ASTRIDE + kk + tg]);
                af[mt][1] = __float_as_uint(Ac[(r0 + 8) * ASTRIDE + kk + tg]);
                af[mt][2] = __float_as_uint(Ac[(r0)     * ASTRIDE + kk + tg + 4]);
                af[mt][3] = __float_as_uint(Ac[(r0 + 8) * ASTRIDE + kk + tg + 4]);
            }
#pragma unroll
            for (int nt = 0; nt < 8; nt++) {
                const int n = wn + nt * 8 + g;
                unsigned b0 = __float_as_uint(Bc[(kk + tg)     * BSTRIDE + n]);
                unsigned b1 = __float_as_uint(Bc[(kk + tg + 4) * BSTRIDE + n]);
#pragma unroll
                for (int mt = 0; mt < 2; mt++)
                    mma_tf32(acc[mt][nt], af[mt][0], af[mt][1], af[mt][2], af[mt][3], b0, b1);
            }
        }
        sid = (sid == 2) ? 0 : sid + 1;
        sid2 = (sid2 == 2) ? 0 : sid2 + 1;
    }

#pragma unroll
    for (int mt = 0; mt < 2; mt++) {
#pragma unroll
        for (int nt = 0; nt < 8; nt++) {
            const int row0 = bm + wm + mt * 16 + g;
            const int col = bn + wn + nt * 8 + 2 * tg;
            *(float2*)&C[(size_t)row0 * N + col] =
                make_float2(acc[mt][nt][0], acc[mt][nt][1]);
            *(float2*)&C[(size_t)(row0 + 8) * N + col] =
                make_float2(acc[mt][nt][2], acc[mt][nt][3]);
        }
    }
#undef LOAD_STAGE
}

__global__ __launch_bounds__(256) void tgemm(const float* __restrict__ A,
                                             const float* __restrict__ B,
                                             float* __restrict__ C,
                                             int M, int N, int K)
{
    tgemm_body(A, B, C, M, N, K);
}

// merged QKV: grid.z selects weight/output
__global__ __launch_bounds__(256) void tgemm_qkv(const float* __restrict__ A,
                                                 const float* __restrict__ B0,
                                                 const float* __restrict__ B1,
                                                 const float* __restrict__ B2,
                                                 float* __restrict__ C0,
                                                 float* __restrict__ C1,
                                                 float* __restrict__ C2,
                                                 int M, int N, int K)
{
    const float* B = (blockIdx.z == 0) ? B0 : (blockIdx.z == 1) ? B1 : B2;
    float* C = (blockIdx.z == 0) ? C0 : (blockIdx.z == 1) ? C1 : C2;
    tgemm_body(A, B, C, M, N, K);
}

// ---------------- gate kernel: 4 rows/block, float4 W loads ----------------
__global__ __launch_bounds__(256) void gate_kernel(const float* __restrict__ x,
                                                   const float* __restrict__ fw,
                                                   const float* __restrict__ fb,
                                                   const float* __restrict__ wl,
                                                   float* __restrict__ lf)
{
    __shared__ float xs[4][2048];
    __shared__ float4 red4[8][8][4];     // [warp][grp][row]
    __shared__ float dots[4][32];
    const int bt0 = blockIdx.x * 4;
    const int tid = threadIdx.x;
    const int warp = tid >> 5, lane = tid & 31;
    const int grp = lane >> 2, koff = lane & 3;

#pragma unroll
    for (int i = 0; i < 8; i++) {
        int idx = tid + 256 * i;
        int row = idx >> 9, c4 = idx & 511;
        *(float4*)&xs[row][c4 * 4] =
            *(const float4*)&x[(size_t)(bt0 + row) * PC + c4 * 4];
    }
    __syncthreads();

    const float* W = (grp < 4) ? fw : wl;
    const int h4 = (grp & 3) * 4;
    float4 s[4];
#pragma unroll
    for (int r = 0; r < 4; r++) s[r] = make_float4(0.f, 0.f, 0.f, 0.f);

    for (int i = 0; i < 64; i++) {
        int c = koff + 4 * warp + 32 * i;
        float4 wv = *(const float4*)&W[c * PH + h4];
#pragma unroll
        for (int r = 0; r < 4; r++) {
            float xv = xs[r][c];
            s[r].x += xv * wv.x; s[r].y += xv * wv.y;
            s[r].z += xv * wv.z; s[r].w += xv * wv.w;
        }
    }
#pragma unroll
    for (int off = 1; off < 4; off <<= 1) {
#pragma unroll
        for (int r = 0; r < 4; r++) {
            s[r].x += __shfl_xor_sync(0xffffffffu, s[r].x, off);
            s[r].y += __shfl_xor_sync(0xffffffffu, s[r].y, off);
            s[r].z += __shfl_xor_sync(0xffffffffu, s[r].z, off);
            s[r].w += __shfl_xor_sync(0xffffffffu, s[r].w, off);
        }
    }
    if (koff == 0) {
#pragma unroll
        for (int r = 0; r < 4; r++) red4[warp][grp][r] = s[r];
    }
    __syncthreads();
    if (tid < 128) {
        int row = tid >> 5, o = tid & 31;
        int gg = o >> 2, comp = o & 3;
        float t = 0.f;
#pragma unroll
        for (int w2 = 0; w2 < 8; w2++)
            t += ((const float*)&red4[w2][gg][row])[comp];
        dots[row][o] = t;
    }
    __syncthreads();
    if (tid < 64) {
        const int row = tid >> 4, hh = tid & 15;
        const int bt = bt0 + row;
        const int b = bt >> 11, t = bt & (PT - 1);
        float fdot = dots[row][hh] + fb[hh];
        float ldot = dots[row][16 + hh];
        float lam = ldot > 0.f ? ldot + 1.f : expf(ldot);
        float logit = fdot * lam;
        float ls = (logit >= 0.f) ? -log1pf(expf(-logit))
                                  : (logit - log1pf(expf(logit)));
        lf[((size_t)(b * PH + hh)) * PT + t] = ls / (lam + 0.001f);
    }
}

// ---------------- cumsum over T per (b,h) ----------------
__global__ __launch_bounds__(256) void cumsum_kernel(const float* __restrict__ lf,
                                                     float* __restrict__ cf)
{
    __shared__ float tot[256];
    const int bh = blockIdx.x, tid = threadIdx.x;
    const float* in = lf + (size_t)bh * PT;
    float* out = cf + (size_t)bh * PT;
    float v[8];
    float r = 0.f;
#pragma unroll
    for (int j = 0; j < 8; j++) { r += in[tid * 8 + j]; v[j] = r; }
    tot[tid] = r;
    __syncthreads();
    for (int off = 1; off < 256; off <<= 1) {
        float t = 0.f;
        if (tid >= off) t = tot[tid - off];
        __syncthreads();
        if (tid >= off) tot[tid] += t;
        __syncthreads();
    }
    float base = tid ? tot[tid - 1] : 0.f;
#pragma unroll
    for (int j = 0; j < 8; j++) out[tid * 8 + j] = v[j] + base;
}

// ---------------- RoPE + RMSNorm, in place on [B,T,H,D] ----------------
// Writes tf32-rounded output (consumed by attention which re-rounds anyway).
__global__ __launch_bounds__(256) void rope_rms_kernel(float* __restrict__ data,
                                                       const float* __restrict__ cosp,
                                                       const float* __restrict__ sinp)
{
    const int wid = blockIdx.x * 8 + (threadIdx.x >> 5);
    const int lane = threadIdx.x & 31;
    const int t = (wid >> 4) & (PT - 1);
    float* row = data + (size_t)wid * PD;
    const int i0 = lane, i1 = lane + 32;
    float x1a = row[i0], x1b = row[i1];
    float x2a = row[i0 + 64], x2b = row[i1 + 64];
    float ca = cosp[t * 64 + i0], cb = cosp[t * 64 + i1];
    float sa = sinp[t * 64 + i0], sb = sinp[t * 64 + i1];
    float o0 = x1a * ca + x2a * sa;
    float o1 = x1b * cb + x2b * sb;
    float o2 = x2a * ca - x1a * sa;
    float o3 = x2b * cb - x1b * sb;
    float ss = o0 * o0 + o1 * o1 + o2 * o2 + o3 * o3;
#pragma unroll
    for (int off = 16; off > 0; off >>= 1) ss += __shfl_xor_sync(0xffffffffu, ss, off);
    float vv = ss * (1.f / 128.f) + 1.1920929e-07f;
    float inv = rsqrtf(vv);
    inv = inv * (1.5f - 0.5f * vv * inv * inv);
    row[i0] = o0 * inv;
    row[i1] = o1 * inv;
    row[i0 + 64] = o2 * inv;
    row[i1 + 64] = o3 * inv;
}

// ---------------- windowed gated attention, tf32 tensor cores ----------------
#define QSTR 132
#define KSTR 132
#define VSTR 136
#define PSTR 68
#define AT_QS 0
#define AT_KS (AT_QS + 128*QSTR)
#define AT_VS (AT_KS + 64*KSTR)
#define AT_PS (AT_VS + 64*VSTR)
#define AT_CFK (AT_PS + 128*PSTR)
#define AT_SMEM ((AT_CFK + 64) * 4)     // 171520 bytes

__global__ __launch_bounds__(256) void attn_mma_kernel(const float* __restrict__ Qg,
                                                       const float* __restrict__ Kg,
                                                       const float* __restrict__ Vg,
                                                       const float* __restrict__ cumF,
                                                       float* __restrict__ Y,
                                                       const int* __restrict__ winp)
{
    extern __shared__ unsigned smu[];
    unsigned* Qs = smu + AT_QS;
    unsigned* Ks = smu + AT_KS;
    unsigned* Vs = smu + AT_VS;
    unsigned* Ps = smu + AT_PS;
    float* cfk = (float*)(smu + AT_CFK);

    const int tid = threadIdx.x;
    const int lane = tid & 31, warp = tid >> 5;
    const int g = lane >> 2, tg = lane & 3;
    const int wm = warp * 16;
    const int qt = blockIdx.x, h = blockIdx.y, b = blockIdx.z;
    const int q0 = qt * 128;
    const int win = *winp;
    const float sm_scale = 0.08838834764831845f;
    const float* cF = cumF + (size_t)(b * PH + h) * PT;

    {
        const size_t base = ((size_t)(b * PT + q0) * PH + h) * PD;
#pragma unroll
        for (int i = 0; i < 16; i++) {
            int idx = tid + 256 * i;
            int r = idx >> 5, d4 = idx & 31;
            float4 qv = *(const float4*)&Qg[base + (size_t)r * PHD + d4 * 4];
            uint4 u;
            u.x = f2tf(qv.x * sm_scale); u.y = f2tf(qv.y * sm_scale);
            u.z = f2tf(qv.z * sm_scale); u.w = f2tf(qv.w * sm_scale);
            *(uint4*)&Qs[r * QSTR + d4 * 4] = u;
        }
    }
    const int rowA = wm + g, rowB = wm + g + 8;
    const float cfqA = cF[q0 + rowA];
    const float cfqB = cF[q0 + rowB];
    const int qiA = q0 + rowA, qiB = q0 + rowB;

    float mA = -1e30f, mB = -1e30f, lA = 0.f, lB = 0.f;
    float acc[16][4];
#pragma unroll
    for (int nt = 0; nt < 16; nt++)
#pragma unroll
        for (int i = 0; i < 4; i++) acc[nt][i] = 0.f;

    const int kt_hi = (q0 + 127) >> 6;
    const int lo = q0 - win + 1;
    const int kt_min = lo > 0 ? (lo >> 6) : 0;

    for (int kt = kt_hi; kt >= kt_min; --kt) {
        const int kb = kt * 64;
        __syncthreads();
        {
            const size_t base = ((size_t)(b * PT + kb) * PH + h) * PD;
#pragma unroll
            for (int i = 0; i < 8; i++) {
                int idx = tid + 256 * i;
                int r = idx >> 5, d4 = idx & 31;
                float4 kv = *(const float4*)&Kg[base + (size_t)r * PHD + d4 * 4];
                uint4 uk;
                uk.x = f2tf(kv.x); uk.y = f2tf(kv.y); uk.z = f2tf(kv.z); uk.w = f2tf(kv.w);
                *(uint4*)&Ks[r * KSTR + d4 * 4] = uk;
                float4 vv = *(const float4*)&Vg[base + (size_t)r * PHD + d4 * 4];
                uint4 uv;
                uv.x = f2tf(vv.x); uv.y = f2tf(vv.y); uv.z = f2tf(vv.z); uv.w = f2tf(vv.w);
                *(uint4*)&Vs[r * VSTR + d4 * 4] = uv;
            }
            if (tid < 64) cfk[tid] = cF[kb + tid];
        }
        __syncthreads();

        float sc_[8][4];
#pragma unroll
        for (int nt = 0; nt < 8; nt++)
#pragma unroll
            for (int i = 0; i < 4; i++) sc_[nt][i] = 0.f;

#pragma unroll
        for (int kk = 0; kk < 128; kk += 8) {
            unsigned a0 = Qs[rowA * QSTR + kk + tg];
            unsigned a1 = Qs[rowB * QSTR + kk + tg];
            unsigned a2 = Qs[rowA * QSTR + kk + tg + 4];
            unsigned a3 = Qs[rowB * QSTR + kk + tg + 4];
#pragma unroll
            for (int nt = 0; nt < 8; nt++) {
                const int n = nt * 8 + g;
                unsigned b0 = Ks[n * KSTR + kk + tg];
                unsigned b1 = Ks[n * KSTR + kk + tg + 4];
                mma_tf32(sc_[nt], a0, a1, a2, a3, b0, b1);
            }
        }

#pragma unroll
        for (int nt = 0; nt < 8; nt++) {
            const int j0 = kb + nt * 8 + 2 * tg;
            const int j1 = j0 + 1;
            const float c0 = cfk[nt * 8 + 2 * tg];
            const float c1 = cfk[nt * 8 + 2 * tg + 1];
            sc_[nt][0] = (j0 <= qiA && qiA - j0 < win) ? sc_[nt][0] + cfqA - c0 : -1e30f;
            sc_[nt][1] = (j1 <= qiA && qiA - j1 < win) ? sc_[nt][1] + cfqA - c1 : -1e30f;
            sc_[nt][2] = (j0 <= qiB && qiB - j0 < win) ? sc_[nt][2] + cfqB - c0 : -1e30f;
            sc_[nt][3] = (j1 <= qiB && qiB - j1 < win) ? sc_[nt][3] + cfqB - c1 : -1e30f;
        }
        float mxA = -1e30f, mxB = -1e30f;
#pragma unroll
        for (int nt = 0; nt < 8; nt++) {
            mxA = fmaxf(mxA, fmaxf(sc_[nt][0], sc_[nt][1]));
            mxB = fmaxf(mxB, fmaxf(sc_[nt][2], sc_[nt][3]));
        }
#pragma unroll
        for (int off = 1; off < 4; off <<= 1) {
            mxA = fmaxf(mxA, __shfl_xor_sync(0xffffffffu, mxA, off));
            mxB = fmaxf(mxB, __shfl_xor_sync(0xffffffffu, mxB, off));
        }
        const float mnA = fmaxf(mA, mxA);
        const float mnB = fmaxf(mB, mxB);
        const float scaA = __expf(mA - mnA);
        const float scaB = __expf(mB - mnB);
        mA = mnA; mB = mnB;

        float rsA = 0.f, rsB = 0.f;
#pragma unroll
        for (int nt = 0; nt < 8; nt++) {
            float p0 = (sc_[nt][0] > -1e29f) ? __expf(sc_[nt][0] - mnA) : 0.f;
            float p1 = (sc_[nt][1] > -1e29f) ? __expf(sc_[nt][1] - mnA) : 0.f;
            float p2 = (sc_[nt][2] > -1e29f) ? __expf(sc_[nt][2] - mnB) : 0.f;
            float p3 = (sc_[nt][3] > -1e29f) ? __expf(sc_[nt][3] - mnB) : 0.f;
            rsA += p0 + p1;
            rsB += p2 + p3;
            uint2 uA = make_uint2(f2tf(p0), f2tf(p1));
            uint2 uB = make_uint2(f2tf(p2), f2tf(p3));
            *(uint2*)&Ps[rowA * PSTR + nt * 8 + 2 * tg] = uA;
            *(uint2*)&Ps[rowB * PSTR + nt * 8 + 2 * tg] = uB;
        }
#pragma unroll
        for (int off = 1; off < 4; off <<= 1) {
            rsA += __shfl_xor_sync(0xffffffffu, rsA, off);
            rsB += __shfl_xor_sync(0xffffffffu, rsB, off);
        }
        lA = lA * scaA + rsA;
        lB = lB * scaB + rsB;
#pragma unroll
        for (int nt = 0; nt < 16; nt++) {
            acc[nt][0] *= scaA; acc[nt][1] *= scaA;
            acc[nt][2] *= scaB; acc[nt][3] *= scaB;
        }
        __syncwarp();

#pragma unroll
        for (int kv = 0; kv < 64; kv += 8) {
            unsigned a0 = Ps[rowA * PSTR + kv + tg];
            unsigned a1 = Ps[rowB * PSTR + kv + tg];
            unsigned a2 = Ps[rowA * PSTR + kv + tg + 4];
            unsigned a3 = Ps[rowB * PSTR + kv + tg + 4];
#pragma unroll
            for (int nt = 0; nt < 16; nt++) {
                const int n = nt * 8 + g;
                unsigned b0 = Vs[(kv + tg) * VSTR + n];
                unsigned b1 = Vs[(kv + tg + 4) * VSTR + n];
                mma_tf32(acc[nt], a0, a1, a2, a3, b0, b1);
            }
        }
        __syncwarp();
    }

    // epilogue: write tf32-rounded Y so the Wo GEMM needs no CVT
    const float invA = 1.f / lA;
    const float invB = 1.f / lB;
    unsigned* Yu = (unsigned*)Y;
#pragma unroll
    for (int nt = 0; nt < 16; nt++) {
        const int col = nt * 8 + 2 * tg;
        size_t oA = ((size_t)(b * PT + q0 + rowA) * PH + h) * PD + col;
        size_t oB = ((size_t)(b * PT + q0 + rowB) * PH + h) * PD + col;
        *(uint2*)&Yu[oA] = make_uint2(f2tf(acc[nt][0] * invA), f2tf(acc[nt][1] * invA));
        *(uint2*)&Yu[oB] = make_uint2(f2tf(acc[nt][2] * invB), f2tf(acc[nt][3] * invB));
    }
}

// ---------------- launch ----------------
extern "C" void kernel_launch(void* const* d_in, const int* in_sizes, int n_in,
                              void* d_out, int out_size)
{
    const float* x   = (const float*)d_in[0];
    const float* cosp= (const float*)d_in[1];
    const float* sinp= (const float*)d_in[2];
    const float* Wq  = (const float*)d_in[3];
    const float* Wk  = (const float*)d_in[4];
    const float* Wv  = (const float*)d_in[5];
    const float* Wo  = (const float*)d_in[6];
    const float* fw  = (const float*)d_in[7];
    const float* fb  = (const float*)d_in[8];
    const float* wl  = (const float*)d_in[9];
    const int*   win = (const int*)d_in[10];
    float* out = (float*)d_out;

    float *q, *k, *v, *y, *lf, *cf, *xt, *wq, *wk, *wv, *wo;
    cudaGetSymbolAddress((void**)&q, g_q);
    cudaGetSymbolAddress((void**)&k, g_k);
    cudaGetSymbolAddress((void**)&v, g_v);
    cudaGetSymbolAddress((void**)&y, g_y);
    cudaGetSymbolAddress((void**)&lf, g_lf);
    cudaGetSymbolAddress((void**)&cf, g_cf);
    cudaGetSymbolAddress((void**)&xt, g_xt);
    cudaGetSymbolAddress((void**)&wq, g_wq);
    cudaGetSymbolAddress((void**)&wk, g_wk);
    cudaGetSymbolAddress((void**)&wv, g_wv);
    cudaGetSymbolAddress((void**)&wo, g_wo);

    cudaFuncSetAttribute(tgemm, cudaFuncAttributeMaxDynamicSharedMemorySize, TG_SMEM);
    cudaFuncSetAttribute(tgemm_qkv, cudaFuncAttributeMaxDynamicSharedMemorySize, TG_SMEM);
    cudaFuncSetAttribute(attn_mma_kernel, cudaFuncAttributeMaxDynamicSharedMemorySize, AT_SMEM);

    // pre-round all GEMM operands to tf32
    tf32_conv<<<(PM * PC / 4 + 255) / 256, 256>>>(x, xt, PM * PC / 4);
    tf32_conv<<<(PC * PHD / 4 + 255) / 256, 256>>>(Wq, wq, PC * PHD / 4);
    tf32_conv<<<(PC * PHD / 4 + 255) / 256, 256>>>(Wk, wk, PC * PHD / 4);
    tf32_conv<<<(PC * PHD / 4 + 255) / 256, 256>>>(Wv, wv, PC * PHD / 4);
    tf32_conv<<<(PC * PC / 4 + 255) / 256, 256>>>(Wo, wo, PC * PC / 4);

    dim3 gq(PHD / 128, PM / 128, 3);              // (16, 32, 3)
    tgemm_qkv<<<gq, 256, TG_SMEM>>>(xt, wq, wk, wv, q, k, v, PM, PHD, PC);

    gate_kernel<<<PM / 4, 256>>>(x, fw, fb, wl, lf);
    cumsum_kernel<<<PB * PH, 256>>>(lf, cf);

    rope_rms_kernel<<<(PB * PT * PH) / 8, 256>>>(q, cosp, sinp);
    rope_rms_kernel<<<(PB * PT * PH) / 8, 256>>>(k, cosp, sinp);

    dim3 ag(PT / 128, PH, PB);                    // (16, 16, 2)
    attn_mma_kernel<<<ag, 256, AT_SMEM>>>(q, k, v, cf, y, win);

    dim3 gg(PC / 128, PM / 128);                  // (16, 32)
    tgemm<<<gg, 256, TG_SMEM>>>(y, wo, out, PM, PC, PC);
}

// round 9
// speedup vs baseline: 2.0810x; 1.3537x over previous
#include <cuda_runtime.h>
#include <cuda_bf16.h>
#include <cuda_fp16.h>
#include <math.h>
#include <cstdint>

// Problem constants (fixed by setup_inputs)
#define PB 2
#define PT 2048
#define PC 2048
#define PH 16
#define PD 128
#define PM (PB*PT)        // 4096 rows of x
#define PHD (PH*PD)       // 2048

// ---------------- scratch (device globals; no allocs allowed) ----------------
__device__ float g_q[PB*PT*PH*PD];
__device__ float g_k[PB*PT*PH*PD];
__device__ float g_v[PB*PT*PH*PD];
__device__ float g_lf[PB*PH*PT];
__device__ float g_cf[PB*PH*PT];
__device__ __half g_xh[PM*PC];       // x, fp16
__device__ __half g_yh[PM*PHD];      // attention output, fp16
__device__ __half g_wqh[PC*PHD];     // Wq^T [N,K], fp16
__device__ __half g_wkh[PC*PHD];
__device__ __half g_wvh[PC*PHD];
__device__ __half g_woh[PC*PC];

__device__ __forceinline__ unsigned f2tf(float f) {
    unsigned u;
    asm("cvt.rna.tf32.f32 %0, %1;" : "=r"(u) : "f"(f));
    return u;
}

__device__ __forceinline__ void cp16s(unsigned saddr, const void* g) {
    asm volatile("cp.async.cg.shared.global [%0], [%1], 16;" :: "r"(saddr), "l"(g));
}

__device__ __forceinline__ void mma_tf32(float* c, unsigned a0, unsigned a1,
                                         unsigned a2, unsigned a3,
                                         unsigned b0, unsigned b1) {
    asm volatile(
        "mma.sync.aligned.m16n8k8.row.col.f32.tf32.tf32.f32 "
        "{%0,%1,%2,%3}, {%4,%5,%6,%7}, {%8,%9}, {%0,%1,%2,%3};"
        : "+f"(c[0]), "+f"(c[1]), "+f"(c[2]), "+f"(c[3])
        : "r"(a0), "r"(a1), "r"(a2), "r"(a3), "r"(b0), "r"(b1));
}

__device__ __forceinline__ void mma_f16(float* c, unsigned a0, unsigned a1,
                                        unsigned a2, unsigned a3,
                                        unsigned b0, unsigned b1) {
    asm volatile(
        "mma.sync.aligned.m16n8k16.row.col.f32.f16.f16.f32 "
        "{%0,%1,%2,%3}, {%4,%5,%6,%7}, {%8,%9}, {%0,%1,%2,%3};"
        : "+f"(c[0]), "+f"(c[1]), "+f"(c[2]), "+f"(c[3])
        : "r"(a0), "r"(a1), "r"(a2), "r"(a3), "r"(b0), "r"(b1));
}

// ================= fp16 tensor-core GEMM: C = A[M,K] @ Bt[N,K]^T =============
// A, Bt fp16; C fp32. 128x128x32 CTA tile, 8 warps (4M x 2N), warp tile 32x64,
// mma.m16n8k16.f16 (fp32 accum), 3-stage cp.async ring.
#define HS 40                           // smem row stride in halfs (80 bytes)
#define HA_BYTES (128*HS*2)             // 10240 per operand tile
#define HSTAGE (2*HA_BYTES)             // 20480
#define HG_SMEM (3*HSTAGE)              // 61440

__device__ __forceinline__ void hgemm_body(const __half* __restrict__ A,
                                           const __half* __restrict__ Bt,
                                           float* __restrict__ C,
                                           int M, int N, int K)
{
    extern __shared__ char smem[];
    unsigned sbase;
    asm("{ .reg .u64 t; cvta.to.shared.u64 t, %1; cvt.u32.u64 %0, t; }"
        : "=r"(sbase) : "l"(smem));

    const int tid = threadIdx.x;
    const int lane = tid & 31, warp = tid >> 5;
    const int g = lane >> 2, tg = lane & 3;
    const int wm = (warp & 3) * 32;
    const int wn = (warp >> 2) * 64;
    const int bm = blockIdx.y * 128, bn = blockIdx.x * 128;

    float acc[2][8][4];
#pragma unroll
    for (int mt = 0; mt < 2; mt++)
#pragma unroll
        for (int nt = 0; nt < 8; nt++)
#pragma unroll
            for (int i = 0; i < 4; i++) acc[mt][nt][i] = 0.f;

    const int r0 = tid >> 2, j = tid & 3;         // 64 rows/pass, 4x16B per row
    const __half* Ag = A + (size_t)(bm + r0) * K + j * 8;
    const __half* Bg = Bt + (size_t)(bn + r0) * K + j * 8;
    const int nT = K / 32;

#define HLOAD(T, S)                                                             \
    {                                                                           \
        unsigned sa = sbase + (S) * HSTAGE;                                     \
        unsigned sb = sa + HA_BYTES;                                            \
        const __half* ga = Ag + (size_t)(T) * 32;                               \
        const __half* gb = Bg + (size_t)(T) * 32;                               \
        _Pragma("unroll")                                                       \
        for (int i = 0; i < 2; i++) {                                           \
            unsigned o = (unsigned)(r0 + 64 * i) * (HS * 2) + j * 16;           \
            cp16s(sa + o, ga + (size_t)(64 * i) * K);                           \
            cp16s(sb + o, gb + (size_t)(64 * i) * K);                           \
        }                                                                       \
        asm volatile("cp.async.commit_group;");                                 \
    }

    HLOAD(0, 0);
    HLOAD(1, 1);

    int sid = 0, sid2 = 2;
    for (int t = 0; t < nT; t++) {
        if (t + 1 < nT) asm volatile("cp.async.wait_group 1;");
        else            asm volatile("cp.async.wait_group 0;");
        __syncthreads();
        if (t + 2 < nT) HLOAD(t + 2, sid2);

        const __half* Ac = (const __half*)(smem + sid * HSTAGE);
        const __half* Bc = (const __half*)(smem + sid * HSTAGE + HA_BYTES);

#pragma unroll
        for (int kk = 0; kk < 32; kk += 16) {
            unsigned af[2][4];
#pragma unroll
            for (int mt = 0; mt < 2; mt++) {
                const int ra = wm + mt * 16 + g;
                af[mt][0] = *(const unsigned*)&Ac[(ra)     * HS + kk + 2 * tg];
                af[mt][1] = *(const unsigned*)&Ac[(ra + 8) * HS + kk + 2 * tg];
                af[mt][2] = *(const unsigned*)&Ac[(ra)     * HS + kk + 2 * tg + 8];
                af[mt][3] = *(const unsigned*)&Ac[(ra + 8) * HS + kk + 2 * tg + 8];
            }
#pragma unroll
            for (int nt = 0; nt < 8; nt++) {
                const int n = wn + nt * 8 + g;
                unsigned b0 = *(const unsigned*)&Bc[n * HS + kk + 2 * tg];
                unsigned b1 = *(const unsigned*)&Bc[n * HS + kk + 2 * tg + 8];
#pragma unroll
                for (int mt = 0; mt < 2; mt++)
                    mma_f16(acc[mt][nt], af[mt][0], af[mt][1], af[mt][2], af[mt][3], b0, b1);
            }
        }
        sid = (sid == 2) ? 0 : sid + 1;
        sid2 = (sid2 == 2) ? 0 : sid2 + 1;
    }
#undef HLOAD

#pragma unroll
    for (int mt = 0; mt < 2; mt++) {
#pragma unroll
        for (int nt = 0; nt < 8; nt++) {
            const int row0 = bm + wm + mt * 16 + g;
            const int col = bn + wn + nt * 8 + 2 * tg;
            *(float2*)&C[(size_t)row0 * N + col] =
                make_float2(acc[mt][nt][0], acc[mt][nt][1]);
            *(float2*)&C[(size_t)(row0 + 8) * N + col] =
                make_float2(acc[mt][nt][2], acc[mt][nt][3]);
        }
    }
}

__global__ __launch_bounds__(256, 2) void hgemm(const __half* __restrict__ A,
                                                const __half* __restrict__ Bt,
                                                float* __restrict__ C,
                                                int M, int N, int K)
{
    hgemm_body(A, Bt, C, M, N, K);
}

__global__ __launch_bounds__(256, 2) void hgemm_qkv(const __half* __restrict__ A,
                                                    const __half* __restrict__ B0,
                                                    const __half* __restrict__ B1,
                                                    const __half* __restrict__ B2,
                                                    float* __restrict__ C0,
                                                    float* __restrict__ C1,
                                                    float* __restrict__ C2,
                                                    int M, int N, int K)
{
    const __half* B = (blockIdx.z == 0) ? B0 : (blockIdx.z == 1) ? B1 : B2;
    float* C = (blockIdx.z == 0) ? C0 : (blockIdx.z == 1) ? C1 : C2;
    hgemm_body(A, B, C, M, N, K);
}

// ---------------- fp32 -> fp16 elementwise ----------------
__global__ __launch_bounds__(256) void f2h_conv(const float* __restrict__ in,
                                                __half* __restrict__ out, int n4)
{
    int i = blockIdx.x * 256 + threadIdx.x;
    if (i < n4) {
        float4 v = ((const float4*)in)[i];
        __half2 h0 = __floats2half2_rn(v.x, v.y);
        __half2 h1 = __floats2half2_rn(v.z, v.w);
        *(uint2*)&out[i * 4] = make_uint2(*(unsigned*)&h0, *(unsigned*)&h1);
    }
}

// ---------------- weight transpose + fp16: D[n][k] = h(W[k][n]) ----------------
__global__ __launch_bounds__(256) void wtrans_h(const float* __restrict__ s0,
                                                const float* __restrict__ s1,
                                                const float* __restrict__ s2,
                                                const float* __restrict__ s3,
                                                __half* __restrict__ d0,
                                                __half* __restrict__ d1,
                                                __half* __restrict__ d2,
                                                __half* __restrict__ d3)
{
    const int z = blockIdx.z;
    const float* S = (z == 0) ? s0 : (z == 1) ? s1 : (z == 2) ? s2 : s3;
    __half* D = (z == 0) ? d0 : (z == 1) ? d1 : (z == 2) ? d2 : d3;
    __shared__ float tile[32][33];
    const int tx = threadIdx.x & 31, ty = threadIdx.x >> 5;   // ty 0..7
    const int col = blockIdx.x * 32 + tx;
#pragma unroll
    for (int jj = 0; jj < 4; jj++)
        tile[ty + 8 * jj][tx] = S[(size_t)(blockIdx.y * 32 + ty + 8 * jj) * 2048 + col];
    __syncthreads();
    const int ocol = blockIdx.y * 32 + tx;
#pragma unroll
    for (int jj = 0; jj < 4; jj++)
        D[(size_t)(blockIdx.x * 32 + ty + 8 * jj) * 2048 + ocol] =
            __float2half_rn(tile[tx][ty + 8 * jj]);
}

// ---------------- gate kernel: 4 rows/block, float4 W loads ----------------
__global__ __launch_bounds__(256) void gate_kernel(const float* __restrict__ x,
                                                   const float* __restrict__ fw,
                                                   const float* __restrict__ fb,
                                                   const float* __restrict__ wl,
                                                   float* __restrict__ lf)
{
    __shared__ float xs[4][2048];
    __shared__ float4 red4[8][8][4];
    __shared__ float dots[4][32];
    const int bt0 = blockIdx.x * 4;
    const int tid = threadIdx.x;
    const int warp = tid >> 5, lane = tid & 31;
    const int grp = lane >> 2, koff = lane & 3;

#pragma unroll
    for (int i = 0; i < 8; i++) {
        int idx = tid + 256 * i;
        int row = idx >> 9, c4 = idx & 511;
        *(float4*)&xs[row][c4 * 4] =
            *(const float4*)&x[(size_t)(bt0 + row) * PC + c4 * 4];
    }
    __syncthreads();

    const float* W = (grp < 4) ? fw : wl;
    const int h4 = (grp & 3) * 4;
    float4 s[4];
#pragma unroll
    for (int r = 0; r < 4; r++) s[r] = make_float4(0.f, 0.f, 0.f, 0.f);

    for (int i = 0; i < 64; i++) {
        int c = koff + 4 * warp + 32 * i;
        float4 wv = *(const float4*)&W[c * PH + h4];
#pragma unroll
        for (int r = 0; r < 4; r++) {
            float xv = xs[r][c];
            s[r].x += xv * wv.x; s[r].y += xv * wv.y;
            s[r].z += xv * wv.z; s[r].w += xv * wv.w;
        }
    }
#pragma unroll
    for (int off = 1; off < 4; off <<= 1) {
#pragma unroll
        for (int r = 0; r < 4; r++) {
            s[r].x += __shfl_xor_sync(0xffffffffu, s[r].x, off);
            s[r].y += __shfl_xor_sync(0xffffffffu, s[r].y, off);
            s[r].z += __shfl_xor_sync(0xffffffffu, s[r].z, off);
            s[r].w += __shfl_xor_sync(0xffffffffu, s[r].w, off);
        }
    }
    if (koff == 0) {
#pragma unroll
        for (int r = 0; r < 4; r++) red4[warp][grp][r] = s[r];
    }
    __syncthreads();
    if (tid < 128) {
        int row = tid >> 5, o = tid & 31;
        int gg = o >> 2, comp = o & 3;
        float t = 0.f;
#pragma unroll
        for (int w2 = 0; w2 < 8; w2++)
            t += ((const float*)&red4[w2][gg][row])[comp];
        dots[row][o] = t;
    }
    __syncthreads();
    if (tid < 64) {
        const int row = tid >> 4, hh = tid & 15;
        const int bt = bt0 + row;
        const int b = bt >> 11, t = bt & (PT - 1);
        float fdot = dots[row][hh] + fb[hh];
        float ldot = dots[row][16 + hh];
        float lam = ldot > 0.f ? ldot + 1.f : expf(ldot);
        float logit = fdot * lam;
        float ls = (logit >= 0.f) ? -log1pf(expf(-logit))
                                  : (logit - log1pf(expf(logit)));
        lf[((size_t)(b * PH + hh)) * PT + t] = ls / (lam + 0.001f);
    }
}

// ---------------- cumsum over T per (b,h) ----------------
__global__ __launch_bounds__(256) void cumsum_kernel(const float* __restrict__ lf,
                                                     float* __restrict__ cf)
{
    __shared__ float tot[256];
    const int bh = blockIdx.x, tid = threadIdx.x;
    const float* in = lf + (size_t)bh * PT;
    float* out = cf + (size_t)bh * PT;
    float v[8];
    float r = 0.f;
#pragma unroll
    for (int jj = 0; jj < 8; jj++) { r += in[tid * 8 + jj]; v[jj] = r; }
    tot[tid] = r;
    __syncthreads();
    for (int off = 1; off < 256; off <<= 1) {
        float t = 0.f;
        if (tid >= off) t = tot[tid - off];
        __syncthreads();
        if (tid >= off) tot[tid] += t;
        __syncthreads();
    }
    float base = tid ? tot[tid - 1] : 0.f;
#pragma unroll
    for (int jj = 0; jj < 8; jj++) out[tid * 8 + jj] = v[jj] + base;
}

// ---------------- RoPE + RMSNorm, in place on [B,T,H,D] ----------------
__global__ __launch_bounds__(256) void rope_rms_kernel(float* __restrict__ data,
                                                       const float* __restrict__ cosp,
                                                       const float* __restrict__ sinp)
{
    const int wid = blockIdx.x * 8 + (threadIdx.x >> 5);
    const int lane = threadIdx.x & 31;
    const int t = (wid >> 4) & (PT - 1);
    float* row = data + (size_t)wid * PD;
    const int i0 = lane, i1 = lane + 32;
    float x1a = row[i0], x1b = row[i1];
    float x2a = row[i0 + 64], x2b = row[i1 + 64];
    float ca = cosp[t * 64 + i0], cb = cosp[t * 64 + i1];
    float sa = sinp[t * 64 + i0], sb = sinp[t * 64 + i1];
    float o0 = x1a * ca + x2a * sa;
    float o1 = x1b * cb + x2b * sb;
    float o2 = x2a * ca - x1a * sa;
    float o3 = x2b * cb - x1b * sb;
    float ss = o0 * o0 + o1 * o1 + o2 * o2 + o3 * o3;
#pragma unroll
    for (int off = 16; off > 0; off >>= 1) ss += __shfl_xor_sync(0xffffffffu, ss, off);
    float vv = ss * (1.f / 128.f) + 1.1920929e-07f;
    float inv = rsqrtf(vv);
    inv = inv * (1.5f - 0.5f * vv * inv * inv);
    row[i0] = o0 * inv;
    row[i1] = o1 * inv;
    row[i0 + 64] = o2 * inv;
    row[i1 + 64] = o3 * inv;
}

// ---------------- windowed gated attention, tf32 (legacy mma) ----------------
#define QSTR 132
#define KSTR 132
#define VSTR 136
#define PSTR 68
#define AT_QS 0
#define AT_KS (AT_QS + 128*QSTR)
#define AT_VS (AT_KS + 64*KSTR)
#define AT_PS (AT_VS + 64*VSTR)
#define AT_CFK (AT_PS + 128*PSTR)
#define AT_SMEM ((AT_CFK + 64) * 4)     // 171520 bytes

__global__ __launch_bounds__(256) void attn_mma_kernel(const float* __restrict__ Qg,
                                                       const float* __restrict__ Kg,
                                                       const float* __restrict__ Vg,
                                                       const float* __restrict__ cumF,
                                                       __half* __restrict__ Yh,
                                                       const int* __restrict__ winp)
{
    extern __shared__ unsigned smu[];
    unsigned* Qs = smu + AT_QS;
    unsigned* Ks = smu + AT_KS;
    unsigned* Vs = smu + AT_VS;
    unsigned* Ps = smu + AT_PS;
    float* cfk = (float*)(smu + AT_CFK);

    const int tid = threadIdx.x;
    const int lane = tid & 31, warp = tid >> 5;
    const int g = lane >> 2, tg = lane & 3;
    const int wm = warp * 16;
    const int qt = blockIdx.x, h = blockIdx.y, b = blockIdx.z;
    const int q0 = qt * 128;
    const int win = *winp;
    const float sm_scale = 0.08838834764831845f;
    const float* cF = cumF + (size_t)(b * PH + h) * PT;

    {
        const size_t base = ((size_t)(b * PT + q0) * PH + h) * PD;
#pragma unroll
        for (int i = 0; i < 16; i++) {
            int idx = tid + 256 * i;
            int r = idx >> 5, d4 = idx & 31;
            float4 qv = *(const float4*)&Qg[base + (size_t)r * PHD + d4 * 4];
            uint4 u;
            u.x = f2tf(qv.x * sm_scale); u.y = f2tf(qv.y * sm_scale);
            u.z = f2tf(qv.z * sm_scale); u.w = f2tf(qv.w * sm_scale);
            *(uint4*)&Qs[r * QSTR + d4 * 4] = u;
        }
    }
    const int rowA = wm + g, rowB = wm + g + 8;
    const float cfqA = cF[q0 + rowA];
    const float cfqB = cF[q0 + rowB];
    const int qiA = q0 + rowA, qiB = q0 + rowB;

    float mA = -1e30f, mB = -1e30f, lA = 0.f, lB = 0.f;
    float acc[16][4];
#pragma unroll
    for (int nt = 0; nt < 16; nt++)
#pragma unroll
        for (int i = 0; i < 4; i++) acc[nt][i] = 0.f;

    const int kt_hi = (q0 + 127) >> 6;
    const int lo = q0 - win + 1;
    const int kt_min = lo > 0 ? (lo >> 6) : 0;

    for (int kt = kt_hi; kt >= kt_min; --kt) {
        const int kb = kt * 64;
        __syncthreads();
        {
            const size_t base = ((size_t)(b * PT + kb) * PH + h) * PD;
#pragma unroll
            for (int i = 0; i < 8; i++) {
                int idx = tid + 256 * i;
                int r = idx >> 5, d4 = idx & 31;
                float4 kv = *(const float4*)&Kg[base + (size_t)r * PHD + d4 * 4];
                uint4 uk;
                uk.x = f2tf(kv.x); uk.y = f2tf(kv.y); uk.z = f2tf(kv.z); uk.w = f2tf(kv.w);
                *(uint4*)&Ks[r * KSTR + d4 * 4] = uk;
                float4 vv = *(const float4*)&Vg[base + (size_t)r * PHD + d4 * 4];
                uint4 uv;
                uv.x = f2tf(vv.x); uv.y = f2tf(vv.y); uv.z = f2tf(vv.z); uv.w = f2tf(vv.w);
                *(uint4*)&Vs[r * VSTR + d4 * 4] = uv;
            }
            if (tid < 64) cfk[tid] = cF[kb + tid];
        }
        __syncthreads();

        float sc_[8][4];
#pragma unroll
        for (int nt = 0; nt < 8; nt++)
#pragma unroll
            for (int i = 0; i < 4; i++) sc_[nt][i] = 0.f;

#pragma unroll
        for (int kk = 0; kk < 128; kk += 8) {
            unsigned a0 = Qs[rowA * QSTR + kk + tg];
            unsigned a1 = Qs[rowB * QSTR + kk + tg];
            unsigned a2 = Qs[rowA * QSTR + kk + tg + 4];
            unsigned a3 = Qs[rowB * QSTR + kk + tg + 4];
#pragma unroll
            for (int nt = 0; nt < 8; nt++) {
                const int n = nt * 8 + g;
                unsigned b0 = Ks[n * KSTR + kk + tg];
                unsigned b1 = Ks[n * KSTR + kk + tg + 4];
                mma_tf32(sc_[nt], a0, a1, a2, a3, b0, b1);
            }
        }

#pragma unroll
        for (int nt = 0; nt < 8; nt++) {
            const int j0 = kb + nt * 8 + 2 * tg;
            const int j1 = j0 + 1;
            const float c0 = cfk[nt * 8 + 2 * tg];
            const float c1 = cfk[nt * 8 + 2 * tg + 1];
            sc_[nt][0] = (j0 <= qiA && qiA - j0 < win) ? sc_[nt][0] + cfqA - c0 : -1e30f;
            sc_[nt][1] = (j1 <= qiA && qiA - j1 < win) ? sc_[nt][1] + cfqA - c1 : -1e30f;
            sc_[nt][2] = (j0 <= qiB && qiB - j0 < win) ? sc_[nt][2] + cfqB - c0 : -1e30f;
            sc_[nt][3] = (j1 <= qiB && qiB - j1 < win) ? sc_[nt][3] + cfqB - c1 : -1e30f;
        }
        float mxA = -1e30f, mxB = -1e30f;
#pragma unroll
        for (int nt = 0; nt < 8; nt++) {
            mxA = fmaxf(mxA, fmaxf(sc_[nt][0], sc_[nt][1]));
            mxB = fmaxf(mxB, fmaxf(sc_[nt][2], sc_[nt][3]));
        }
#pragma unroll
        for (int off = 1; off < 4; off <<= 1) {
            mxA = fmaxf(mxA, __shfl_xor_sync(0xffffffffu, mxA, off));
            mxB = fmaxf(mxB, __shfl_xor_sync(0xffffffffu, mxB, off));
        }
        const float mnA = fmaxf(mA, mxA);
        const float mnB = fmaxf(mB, mxB);
        const float scaA = __expf(mA - mnA);
        const float scaB = __expf(mB - mnB);
        mA = mnA; mB = mnB;

        float rsA = 0.f, rsB = 0.f;
#pragma unroll
        for (int nt = 0; nt < 8; nt++) {
            float p0 = (sc_[nt][0] > -1e29f) ? __expf(sc_[nt][0] - mnA) : 0.f;
            float p1 = (sc_[nt][1] > -1e29f) ? __expf(sc_[nt][1] - mnA) : 0.f;
            float p2 = (sc_[nt][2] > -1e29f) ? __expf(sc_[nt][2] - mnB) : 0.f;
            float p3 = (sc_[nt][3] > -1e29f) ? __expf(sc_[nt][3] - mnB) : 0.f;
            rsA += p0 + p1;
            rsB += p2 + p3;
            uint2 uA = make_uint2(f2tf(p0), f2tf(p1));
            uint2 uB = make_uint2(f2tf(p2), f2tf(p3));
            *(uint2*)&Ps[rowA * PSTR + nt * 8 + 2 * tg] = uA;
            *(uint2*)&Ps[rowB * PSTR + nt * 8 + 2 * tg] = uB;
        }
#pragma unroll
        for (int off = 1; off < 4; off <<= 1) {
            rsA += __shfl_xor_sync(0xffffffffu, rsA, off);
            rsB += __shfl_xor_sync(0xffffffffu, rsB, off);
        }
        lA = lA * scaA + rsA;
        lB = lB * scaB + rsB;
#pragma unroll
        for (int nt = 0; nt < 16; nt++) {
            acc[nt][0] *= scaA; acc[nt][1] *= scaA;
            acc[nt][2] *= scaB; acc[nt][3] *= scaB;
        }
        __syncwarp();

#pragma unroll
        for (int kv = 0; kv < 64; kv += 8) {
            unsigned a0 = Ps[rowA * PSTR + kv + tg];
            unsigned a1 = Ps[rowB * PSTR + kv + tg];
            unsigned a2 = Ps[rowA * PSTR + kv + tg + 4];
            unsigned a3 = Ps[rowB * PSTR + kv + tg + 4];
#pragma unroll
            for (int nt = 0; nt < 16; nt++) {
                const int n = nt * 8 + g;
                unsigned b0 = Vs[(kv + tg) * VSTR + n];
                unsigned b1 = Vs[(kv + tg + 4) * VSTR + n];
                mma_tf32(acc[nt], a0, a1, a2, a3, b0, b1);
            }
        }
        __syncwarp();
    }

    // epilogue: write fp16 Y (feeds fp16 Wo GEMM directly)
    const float invA = 1.f / lA;
    const float invB = 1.f / lB;
#pragma unroll
    for (int nt = 0; nt < 16; nt++) {
        const int col = nt * 8 + 2 * tg;
        size_t oA = ((size_t)(b * PT + q0 + rowA) * PH + h) * PD + col;
        size_t oB = ((size_t)(b * PT + q0 + rowB) * PH + h) * PD + col;
        __half2 hA = __floats2half2_rn(acc[nt][0] * invA, acc[nt][1] * invA);
        __half2 hB = __floats2half2_rn(acc[nt][2] * invB, acc[nt][3] * invB);
        *(unsigned*)&Yh[oA] = *(unsigned*)&hA;
        *(unsigned*)&Yh[oB] = *(unsigned*)&hB;
    }
}

// ---------------- launch ----------------
extern "C" void kernel_launch(void* const* d_in, const int* in_sizes, int n_in,
                              void* d_out, int out_size)
{
    const float* x   = (const float*)d_in[0];
    const float* cosp= (const float*)d_in[1];
    const float* sinp= (const float*)d_in[2];
    const float* Wq  = (const float*)d_in[3];
    const float* Wk  = (const float*)d_in[4];
    const float* Wv  = (const float*)d_in[5];
    const float* Wo  = (const float*)d_in[6];
    const float* fw  = (const float*)d_in[7];
    const float* fb  = (const float*)d_in[8];
    const float* wl  = (const float*)d_in[9];
    const int*   win = (const int*)d_in[10];
    float* out = (float*)d_out;

    float *q, *k, *v, *lf, *cf;
    __half *xh, *yh, *wqh, *wkh, *wvh, *woh;
    cudaGetSymbolAddress((void**)&q, g_q);
    cudaGetSymbolAddress((void**)&k, g_k);
    cudaGetSymbolAddress((void**)&v, g_v);
    cudaGetSymbolAddress((void**)&lf, g_lf);
    cudaGetSymbolAddress((void**)&cf, g_cf);
    cudaGetSymbolAddress((void**)&xh, g_xh);
    cudaGetSymbolAddress((void**)&yh, g_yh);
    cudaGetSymbolAddress((void**)&wqh, g_wqh);
    cudaGetSymbolAddress((void**)&wkh, g_wkh);
    cudaGetSymbolAddress((void**)&wvh, g_wvh);
    cudaGetSymbolAddress((void**)&woh, g_woh);

    cudaFuncSetAttribute(hgemm, cudaFuncAttributeMaxDynamicSharedMemorySize, HG_SMEM);
    cudaFuncSetAttribute(hgemm_qkv, cudaFuncAttributeMaxDynamicSharedMemorySize, HG_SMEM);
    cudaFuncSetAttribute(attn_mma_kernel, cudaFuncAttributeMaxDynamicSharedMemorySize, AT_SMEM);

    // 0: x -> fp16
    f2h_conv<<<(PM * PC / 4 + 255) / 256, 256>>>(x, xh, PM * PC / 4);
    // 1: weights -> transposed [N,K] fp16
    dim3 wt(64, 64, 4);
    wtrans_h<<<wt, 256>>>(Wq, Wk, Wv, Wo, wqh, wkh, wvh, woh);
    // 2,3: gates
    gate_kernel<<<PM / 4, 256>>>(x, fw, fb, wl, lf);
    cumsum_kernel<<<PB * PH, 256>>>(lf, cf);
    // 4: QKV GEMM (fp16 tensor cores) — profiled slot
    dim3 gq(PHD / 128, PM / 128, 3);              // (16, 32, 3)
    hgemm_qkv<<<gq, 256, HG_SMEM>>>(xh, wqh, wkh, wvh, q, k, v, PM, PHD, PC);
    // 5,6: rope+rms
    rope_rms_kernel<<<(PB * PT * PH) / 8, 256>>>(q, cosp, sinp);
    rope_rms_kernel<<<(PB * PT * PH) / 8, 256>>>(k, cosp, sinp);
    // 7: attention (tf32), writes fp16 Y
    dim3 ag(PT / 128, PH, PB);                    // (16, 16, 2)
    attn_mma_kernel<<<ag, 256, AT_SMEM>>>(q, k, v, cf, yh, win);
    // 8: Wo GEMM (fp16)
    dim3 gg(PC / 128, PM / 128);                  // (16, 32)
    hgemm<<<gg, 256, HG_SMEM>>>(yh, woh, out, PM, PC, PC);
}

// round 10
// speedup vs baseline: 2.4915x; 1.1973x over previous
#include <cuda_runtime.h>
#include <cuda_bf16.h>
#include <cuda_fp16.h>
#include <math.h>
#include <cstdint>

// Problem constants (fixed by setup_inputs)
#define PB 2
#define PT 2048
#define PC 2048
#define PH 16
#define PD 128
#define PM (PB*PT)        // 4096 rows of x
#define PHD (PH*PD)       // 2048

// ---------------- scratch (device globals; no allocs allowed) ----------------
__device__ float g_q[PB*PT*PH*PD];
__device__ float g_k[PB*PT*PH*PD];
__device__ float g_v[PB*PT*PH*PD];
__device__ float g_lf[PB*PH*PT];
__device__ float g_cf[PB*PH*PT];
__device__ __half g_qh[PB*PT*PH*PD]; // rope+rms output, fp16, q pre-scaled
__device__ __half g_kh[PB*PT*PH*PD];
__device__ __half g_xh[PM*PC];       // x, fp16
__device__ __half g_yh[PM*PHD];      // attention output, fp16
__device__ __half g_wqh[PC*PHD];     // Wq^T [N,K], fp16
__device__ __half g_wkh[PC*PHD];
__device__ __half g_wvh[PC*PHD];
__device__ __half g_woh[PC*PC];

__device__ __forceinline__ unsigned f2tf(float f) {
    unsigned u;
    asm("cvt.rna.tf32.f32 %0, %1;" : "=r"(u) : "f"(f));
    return u;
}

__device__ __forceinline__ void cp16s(unsigned saddr, const void* g) {
    asm volatile("cp.async.cg.shared.global [%0], [%1], 16;" :: "r"(saddr), "l"(g));
}

__device__ __forceinline__ void mma_tf32(float* c, unsigned a0, unsigned a1,
                                         unsigned a2, unsigned a3,
                                         unsigned b0, unsigned b1) {
    asm volatile(
        "mma.sync.aligned.m16n8k8.row.col.f32.tf32.tf32.f32 "
        "{%0,%1,%2,%3}, {%4,%5,%6,%7}, {%8,%9}, {%0,%1,%2,%3};"
        : "+f"(c[0]), "+f"(c[1]), "+f"(c[2]), "+f"(c[3])
        : "r"(a0), "r"(a1), "r"(a2), "r"(a3), "r"(b0), "r"(b1));
}

__device__ __forceinline__ void mma_f16(float* c, unsigned a0, unsigned a1,
                                        unsigned a2, unsigned a3,
                                        unsigned b0, unsigned b1) {
    asm volatile(
        "mma.sync.aligned.m16n8k16.row.col.f32.f16.f16.f32 "
        "{%0,%1,%2,%3}, {%4,%5,%6,%7}, {%8,%9}, {%0,%1,%2,%3};"
        : "+f"(c[0]), "+f"(c[1]), "+f"(c[2]), "+f"(c[3])
        : "r"(a0), "r"(a1), "r"(a2), "r"(a3), "r"(b0), "r"(b1));
}

// ================= fp16 tensor-core GEMM: C = A[M,K] @ Bt[N,K]^T =============
// 128x128x64 CTA k-tiles, 8 warps, warp tile 32x64, 3-stage cp.async ring.
#define HS 72                           // smem row stride in halfs (144 bytes)
#define HTILE (128*HS*2)                // 18432 B per operand tile
#define HSTAGE (2*HTILE)                // 36864
#define HG_SMEM (3*HSTAGE)              // 110592

__device__ __forceinline__ void hgemm_body(const __half* __restrict__ A,
                                           const __half* __restrict__ Bt,
                                           float* __restrict__ C,
                                           int M, int N, int K)
{
    extern __shared__ char smem[];
    unsigned sbase;
    asm("{ .reg .u64 t; cvta.to.shared.u64 t, %1; cvt.u32.u64 %0, t; }"
        : "=r"(sbase) : "l"(smem));

    const int tid = threadIdx.x;
    const int lane = tid & 31, warp = tid >> 5;
    const int g = lane >> 2, tg = lane & 3;
    const int wm = (warp & 3) * 32;
    const int wn = (warp >> 2) * 64;
    const int bm = blockIdx.y * 128, bn = blockIdx.x * 128;

    float acc[2][8][4];
#pragma unroll
    for (int mt = 0; mt < 2; mt++)
#pragma unroll
        for (int nt = 0; nt < 8; nt++)
#pragma unroll
            for (int i = 0; i < 4; i++) acc[mt][nt][i] = 0.f;

    const int r0 = tid >> 3, cc = tid & 7;       // 32 rows/pass, 8x16B per row
    const __half* Ag = A + (size_t)(bm + r0) * K + cc * 8;
    const __half* Bg = Bt + (size_t)(bn + r0) * K + cc * 8;
    const int nT = K / 64;

#define HLOAD(T, S)                                                             \
    {                                                                           \
        unsigned sa = sbase + (S) * HSTAGE + r0 * 144 + cc * 16;                \
        const __half* ga = Ag + (size_t)(T) * 64;                               \
        const __half* gb = Bg + (size_t)(T) * 64;                               \
        _Pragma("unroll")                                                       \
        for (int i = 0; i < 4; i++) {                                           \
            cp16s(sa + i * (32 * 144),         ga + (size_t)(32 * i) * K);      \
            cp16s(sa + HTILE + i * (32 * 144), gb + (size_t)(32 * i) * K);      \
        }                                                                       \
        asm volatile("cp.async.commit_group;");                                 \
    }

    HLOAD(0, 0);
    HLOAD(1, 1);

    int sid = 0, sid2 = 2;
    for (int t = 0; t < nT; t++) {
        if (t + 1 < nT) asm volatile("cp.async.wait_group 1;");
        else            asm volatile("cp.async.wait_group 0;");
        __syncthreads();
        if (t + 2 < nT) HLOAD(t + 2, sid2);

        const __half* Ac = (const __half*)(smem + sid * HSTAGE);
        const __half* Bc = (const __half*)(smem + sid * HSTAGE + HTILE);

#pragma unroll
        for (int kk = 0; kk < 64; kk += 16) {
            unsigned af[2][4];
#pragma unroll
            for (int mt = 0; mt < 2; mt++) {
                const int ra = wm + mt * 16 + g;
                af[mt][0] = *(const unsigned*)&Ac[(ra)     * HS + kk + 2 * tg];
                af[mt][1] = *(const unsigned*)&Ac[(ra + 8) * HS + kk + 2 * tg];
                af[mt][2] = *(const unsigned*)&Ac[(ra)     * HS + kk + 2 * tg + 8];
                af[mt][3] = *(const unsigned*)&Ac[(ra + 8) * HS + kk + 2 * tg + 8];
            }
#pragma unroll
            for (int nt = 0; nt < 8; nt++) {
                const int n = wn + nt * 8 + g;
                unsigned b0 = *(const unsigned*)&Bc[n * HS + kk + 2 * tg];
                unsigned b1 = *(const unsigned*)&Bc[n * HS + kk + 2 * tg + 8];
#pragma unroll
                for (int mt = 0; mt < 2; mt++)
                    mma_f16(acc[mt][nt], af[mt][0], af[mt][1], af[mt][2], af[mt][3], b0, b1);
            }
        }
        sid = (sid == 2) ? 0 : sid + 1;
        sid2 = (sid2 == 2) ? 0 : sid2 + 1;
    }
#undef HLOAD

#pragma unroll
    for (int mt = 0; mt < 2; mt++) {
#pragma unroll
        for (int nt = 0; nt < 8; nt++) {
            const int row0 = bm + wm + mt * 16 + g;
            const int col = bn + wn + nt * 8 + 2 * tg;
            *(float2*)&C[(size_t)row0 * N + col] =
                make_float2(acc[mt][nt][0], acc[mt][nt][1]);
            *(float2*)&C[(size_t)(row0 + 8) * N + col] =
                make_float2(acc[mt][nt][2], acc[mt][nt][3]);
        }
    }
}

__global__ __launch_bounds__(256, 2) void hgemm(const __half* __restrict__ A,
                                                const __half* __restrict__ Bt,
                                                float* __restrict__ C,
                                                int M, int N, int K)
{
    hgemm_body(A, Bt, C, M, N, K);
}

__global__ __launch_bounds__(256, 2) void hgemm_qkv(const __half* __restrict__ A,
                                                    const __half* __restrict__ B0,
                                                    const __half* __restrict__ B1,
                                                    const __half* __restrict__ B2,
                                                    float* __restrict__ C0,
                                                    float* __restrict__ C1,
                                                    float* __restrict__ C2,
                                                    int M, int N, int K)
{
    const __half* B = (blockIdx.z == 0) ? B0 : (blockIdx.z == 1) ? B1 : B2;
    float* C = (blockIdx.z == 0) ? C0 : (blockIdx.z == 1) ? C1 : C2;
    hgemm_body(A, B, C, M, N, K);
}

// ---------------- fp32 -> fp16 elementwise ----------------
__global__ __launch_bounds__(256) void f2h_conv(const float* __restrict__ in,
                                                __half* __restrict__ out, int n4)
{
    int i = blockIdx.x * 256 + threadIdx.x;
    if (i < n4) {
        float4 v = ((const float4*)in)[i];
        __half2 h0 = __floats2half2_rn(v.x, v.y);
        __half2 h1 = __floats2half2_rn(v.z, v.w);
        *(uint2*)&out[i * 4] = make_uint2(*(unsigned*)&h0, *(unsigned*)&h1);
    }
}

// ---------------- weight transpose + fp16: D[n][k] = h(W[k][n]) ----------------
__global__ __launch_bounds__(256) void wtrans_h(const float* __restrict__ s0,
                                                const float* __restrict__ s1,
                                                const float* __restrict__ s2,
                                                const float* __restrict__ s3,
                                                __half* __restrict__ d0,
                                                __half* __restrict__ d1,
                                                __half* __restrict__ d2,
                                                __half* __restrict__ d3)
{
    const int z = blockIdx.z;
    const float* S = (z == 0) ? s0 : (z == 1) ? s1 : (z == 2) ? s2 : s3;
    __half* D = (z == 0) ? d0 : (z == 1) ? d1 : (z == 2) ? d2 : d3;
    __shared__ float tile[32][33];
    const int tx = threadIdx.x & 31, ty = threadIdx.x >> 5;   // ty 0..7
    const int col = blockIdx.x * 32 + tx;
#pragma unroll
    for (int jj = 0; jj < 4; jj++)
        tile[ty + 8 * jj][tx] = S[(size_t)(blockIdx.y * 32 + ty + 8 * jj) * 2048 + col];
    __syncthreads();
    const int ocol = blockIdx.y * 32 + tx;
#pragma unroll
    for (int jj = 0; jj < 4; jj++)
        D[(size_t)(blockIdx.x * 32 + ty + 8 * jj) * 2048 + ocol] =
            __float2half_rn(tile[tx][ty + 8 * jj]);
}

// ---------------- gate kernel: 4 rows/block, float4 W loads ----------------
__global__ __launch_bounds__(256) void gate_kernel(const float* __restrict__ x,
                                                   const float* __restrict__ fw,
                                                   const float* __restrict__ fb,
                                                   const float* __restrict__ wl,
                                                   float* __restrict__ lf)
{
    __shared__ float xs[4][2048];
    __shared__ float4 red4[8][8][4];
    __shared__ float dots[4][32];
    const int bt0 = blockIdx.x * 4;
    const int tid = threadIdx.x;
    const int warp = tid >> 5, lane = tid & 31;
    const int grp = lane >> 2, koff = lane & 3;

#pragma unroll
    for (int i = 0; i < 8; i++) {
        int idx = tid + 256 * i;
        int row = idx >> 9, c4 = idx & 511;
        *(float4*)&xs[row][c4 * 4] =
            *(const float4*)&x[(size_t)(bt0 + row) * PC + c4 * 4];
    }
    __syncthreads();

    const float* W = (grp < 4) ? fw : wl;
    const int h4 = (grp & 3) * 4;
    float4 s[4];
#pragma unroll
    for (int r = 0; r < 4; r++) s[r] = make_float4(0.f, 0.f, 0.f, 0.f);

    for (int i = 0; i < 64; i++) {
        int c = koff + 4 * warp + 32 * i;
        float4 wv = *(const float4*)&W[c * PH + h4];
#pragma unroll
        for (int r = 0; r < 4; r++) {
            float xv = xs[r][c];
            s[r].x += xv * wv.x; s[r].y += xv * wv.y;
            s[r].z += xv * wv.z; s[r].w += xv * wv.w;
        }
    }
#pragma unroll
    for (int off = 1; off < 4; off <<= 1) {
#pragma unroll
        for (int r = 0; r < 4; r++) {
            s[r].x += __shfl_xor_sync(0xffffffffu, s[r].x, off);
            s[r].y += __shfl_xor_sync(0xffffffffu, s[r].y, off);
            s[r].z += __shfl_xor_sync(0xffffffffu, s[r].z, off);
            s[r].w += __shfl_xor_sync(0xffffffffu, s[r].w, off);
        }
    }
    if (koff == 0) {
#pragma unroll
        for (int r = 0; r < 4; r++) red4[warp][grp][r] = s[r];
    }
    __syncthreads();
    if (tid < 128) {
        int row = tid >> 5, o = tid & 31;
        int gg = o >> 2, comp = o & 3;
        float t = 0.f;
#pragma unroll
        for (int w2 = 0; w2 < 8; w2++)
            t += ((const float*)&red4[w2][gg][row])[comp];
        dots[row][o] = t;
    }
    __syncthreads();
    if (tid < 64) {
        const int row = tid >> 4, hh = tid & 15;
        const int bt = bt0 + row;
        const int b = bt >> 11, t = bt & (PT - 1);
        float fdot = dots[row][hh] + fb[hh];
        float ldot = dots[row][16 + hh];
        float lam = ldot > 0.f ? ldot + 1.f : expf(ldot);
        float logit = fdot * lam;
        float ls = (logit >= 0.f) ? -log1pf(expf(-logit))
                                  : (logit - log1pf(expf(logit)));
        lf[((size_t)(b * PH + hh)) * PT + t] = ls / (lam + 0.001f);
    }
}

// ---------------- cumsum over T per (b,h) ----------------
__global__ __launch_bounds__(256) void cumsum_kernel(const float* __restrict__ lf,
                                                     float* __restrict__ cf)
{
    __shared__ float tot[256];
    const int bh = blockIdx.x, tid = threadIdx.x;
    const float* in = lf + (size_t)bh * PT;
    float* out = cf + (size_t)bh * PT;
    float v[8];
    float r = 0.f;
#pragma unroll
    for (int jj = 0; jj < 8; jj++) { r += in[tid * 8 + jj]; v[jj] = r; }
    tot[tid] = r;
    __syncthreads();
    for (int off = 1; off < 256; off <<= 1) {
        float t = 0.f;
        if (tid >= off) t = tot[tid - off];
        __syncthreads();
        if (tid >= off) tot[tid] += t;
        __syncthreads();
    }
    float base = tid ? tot[tid - 1] : 0.f;
#pragma unroll
    for (int jj = 0; jj < 8; jj++) out[tid * 8 + jj] = v[jj] + base;
}

// ---------- RoPE + RMSNorm: fp32 in, fp16 out (optionally pre-scaled) --------
__global__ __launch_bounds__(256) void rope_rms_h(const float* __restrict__ in,
                                                  __half* __restrict__ outh,
                                                  const float* __restrict__ cosp,
                                                  const float* __restrict__ sinp,
                                                  float scale)
{
    const int wid = blockIdx.x * 8 + (threadIdx.x >> 5);
    const int lane = threadIdx.x & 31;
    const int t = (wid >> 4) & (PT - 1);
    const float* row = in + (size_t)wid * PD;
    __half* orow = outh + (size_t)wid * PD;
    const int i0 = lane, i1 = lane + 32;
    float x1a = row[i0], x1b = row[i1];
    float x2a = row[i0 + 64], x2b = row[i1 + 64];
    float ca = cosp[t * 64 + i0], cb = cosp[t * 64 + i1];
    float sa = sinp[t * 64 + i0], sb = sinp[t * 64 + i1];
    float o0 = x1a * ca + x2a * sa;
    float o1 = x1b * cb + x2b * sb;
    float o2 = x2a * ca - x1a * sa;
    float o3 = x2b * cb - x1b * sb;
    float ss = o0 * o0 + o1 * o1 + o2 * o2 + o3 * o3;
#pragma unroll
    for (int off = 16; off > 0; off >>= 1) ss += __shfl_xor_sync(0xffffffffu, ss, off);
    float vv = ss * (1.f / 128.f) + 1.1920929e-07f;
    float inv = rsqrtf(vv);
    inv = inv * (1.5f - 0.5f * vv * inv * inv);
    inv *= scale;
    orow[i0] = __float2half_rn(o0 * inv);
    orow[i1] = __float2half_rn(o1 * inv);
    orow[i0 + 64] = __float2half_rn(o2 * inv);
    orow[i1 + 64] = __float2half_rn(o3 * inv);
}

// ------------- windowed gated attention: fp16 QK^T + tf32 PV -----------------
// smem bytes layout
#define SQ_OFF 0                        // 128 x 272B fp16 Q (stride 136 halfs)
#define SK_OFF 34816                    // 64 x 272B fp16 K
#define SV_OFF 52224                    // 64 x 136 words tf32 V
#define SP_OFF 87040                    // 128 x 68 words tf32 P
#define SC_OFF 121856                   // 64 floats cumF(k)
#define AT_SMEM 122112
#define VSTR 136
#define PSTR 68

__global__ __launch_bounds__(256) void attn_mma_kernel(const __half* __restrict__ Qh,
                                                       const __half* __restrict__ Kh,
                                                       const float* __restrict__ Vg,
                                                       const float* __restrict__ cumF,
                                                       __half* __restrict__ Yh,
                                                       const int* __restrict__ winp)
{
    extern __shared__ char sm8[];
    unsigned sb;
    asm("{ .reg .u64 t; cvta.to.shared.u64 t, %1; cvt.u32.u64 %0, t; }"
        : "=r"(sb) : "l"(sm8));
    __half* Qs = (__half*)sm8;
    __half* Ks = (__half*)(sm8 + SK_OFF);
    unsigned* Vs = (unsigned*)(sm8 + SV_OFF);
    unsigned* Ps = (unsigned*)(sm8 + SP_OFF);
    float* cfk = (float*)(sm8 + SC_OFF);

    const int tid = threadIdx.x;
    const int lane = tid & 31, warp = tid >> 5;
    const int g = lane >> 2, tg = lane & 3;
    const int wm = warp * 16;
    const int qt = blockIdx.x, h = blockIdx.y, b = blockIdx.z;
    const int q0 = qt * 128;
    const int win = *winp;
    const float* cF = cumF + (size_t)(b * PH + h) * PT;

    // Q tile via cp.async (fp16, already scaled)
    {
        const __half* qg = Qh + ((size_t)(b * PT + q0) * PH + h) * PD;
#pragma unroll
        for (int i = 0; i < 8; i++) {
            int idx = tid + 256 * i;
            int r = idx >> 4, c = idx & 15;
            cp16s(sb + SQ_OFF + r * 272 + c * 16, qg + (size_t)r * PHD + c * 8);
        }
        asm volatile("cp.async.commit_group;");
    }
    const int rowA = wm + g, rowB = wm + g + 8;
    const float cfqA = cF[q0 + rowA];
    const float cfqB = cF[q0 + rowB];
    const int qiA = q0 + rowA, qiB = q0 + rowB;

    float mA = -1e30f, mB = -1e30f, lA = 0.f, lB = 0.f;
    float acc[16][4];
#pragma unroll
    for (int nt = 0; nt < 16; nt++)
#pragma unroll
        for (int i = 0; i < 4; i++) acc[nt][i] = 0.f;

    const int kt_hi = (q0 + 127) >> 6;
    const int lo = q0 - win + 1;
    const int kt_min = lo > 0 ? (lo >> 6) : 0;

    for (int kt = kt_hi; kt >= kt_min; --kt) {
        const int kb = kt * 64;
        __syncthreads();
        // K tile via cp.async (fp16)
        {
            const __half* kg = Kh + ((size_t)(b * PT + kb) * PH + h) * PD;
#pragma unroll
            for (int i = 0; i < 4; i++) {
                int idx = tid + 256 * i;
                int r = idx >> 4, c = idx & 15;
                cp16s(sb + SK_OFF + r * 272 + c * 16, kg + (size_t)r * PHD + c * 8);
            }
            asm volatile("cp.async.commit_group;");
        }
        // V tile: fp32 -> tf32, manual
        {
            const size_t base = ((size_t)(b * PT + kb) * PH + h) * PD;
#pragma unroll
            for (int i = 0; i < 8; i++) {
                int idx = tid + 256 * i;
                int r = idx >> 5, d4 = idx & 31;
                float4 vv = *(const float4*)&Vg[base + (size_t)r * PHD + d4 * 4];
                uint4 uv;
                uv.x = f2tf(vv.x); uv.y = f2tf(vv.y); uv.z = f2tf(vv.z); uv.w = f2tf(vv.w);
                *(uint4*)&Vs[r * VSTR + d4 * 4] = uv;
            }
            if (tid < 64) cfk[tid] = cF[kb + tid];
        }
        asm volatile("cp.async.wait_group 0;");
        __syncthreads();

        // ---- S = Q K^T, fp16 m16n8k16, 8 k-steps ----
        float sc_[8][4];
#pragma unroll
        for (int nt = 0; nt < 8; nt++)
#pragma unroll
            for (int i = 0; i < 4; i++) sc_[nt][i] = 0.f;

#pragma unroll
        for (int kk = 0; kk < 128; kk += 16) {
            unsigned a0 = *(const unsigned*)&Qs[rowA * 136 + kk + 2 * tg];
            unsigned a1 = *(const unsigned*)&Qs[rowB * 136 + kk + 2 * tg];
            unsigned a2 = *(const unsigned*)&Qs[rowA * 136 + kk + 2 * tg + 8];
            unsigned a3 = *(const unsigned*)&Qs[rowB * 136 + kk + 2 * tg + 8];
#pragma unroll
            for (int nt = 0; nt < 8; nt++) {
                const int n = nt * 8 + g;
                unsigned b0 = *(const unsigned*)&Ks[n * 136 + kk + 2 * tg];
                unsigned b1 = *(const unsigned*)&Ks[n * 136 + kk + 2 * tg + 8];
                mma_f16(sc_[nt], a0, a1, a2, a3, b0, b1);
            }
        }

        // ---- bias + mask + online softmax ----
#pragma unroll
        for (int nt = 0; nt < 8; nt++) {
            const int j0 = kb + nt * 8 + 2 * tg;
            const int j1 = j0 + 1;
            const float c0 = cfk[nt * 8 + 2 * tg];
            const float c1 = cfk[nt * 8 + 2 * tg + 1];
            sc_[nt][0] = (j0 <= qiA && qiA - j0 < win) ? sc_[nt][0] + cfqA - c0 : -1e30f;
            sc_[nt][1] = (j1 <= qiA && qiA - j1 < win) ? sc_[nt][1] + cfqA - c1 : -1e30f;
            sc_[nt][2] = (j0 <= qiB && qiB - j0 < win) ? sc_[nt][2] + cfqB - c0 : -1e30f;
            sc_[nt][3] = (j1 <= qiB && qiB - j1 < win) ? sc_[nt][3] + cfqB - c1 : -1e30f;
        }
        float mxA = -1e30f, mxB = -1e30f;
#pragma unroll
        for (int nt = 0; nt < 8; nt++) {
            mxA = fmaxf(mxA, fmaxf(sc_[nt][0], sc_[nt][1]));
            mxB = fmaxf(mxB, fmaxf(sc_[nt][2], sc_[nt][3]));
        }
#pragma unroll
        for (int off = 1; off < 4; off <<= 1) {
            mxA = fmaxf(mxA, __shfl_xor_sync(0xffffffffu, mxA, off));
            mxB = fmaxf(mxB, __shfl_xor_sync(0xffffffffu, mxB, off));
        }
        const float mnA = fmaxf(mA, mxA);
        const float mnB = fmaxf(mB, mxB);
        const float scaA = __expf(mA - mnA);
        const float scaB = __expf(mB - mnB);
        mA = mnA; mB = mnB;

        float rsA = 0.f, rsB = 0.f;
#pragma unroll
        for (int nt = 0; nt < 8; nt++) {
            float p0 = (sc_[nt][0] > -1e29f) ? __expf(sc_[nt][0] - mnA) : 0.f;
            float p1 = (sc_[nt][1] > -1e29f) ? __expf(sc_[nt][1] - mnA) : 0.f;
            float p2 = (sc_[nt][2] > -1e29f) ? __expf(sc_[nt][2] - mnB) : 0.f;
            float p3 = (sc_[nt][3] > -1e29f) ? __expf(sc_[nt][3] - mnB) : 0.f;
            rsA += p0 + p1;
            rsB += p2 + p3;
            uint2 uA = make_uint2(f2tf(p0), f2tf(p1));
            uint2 uB = make_uint2(f2tf(p2), f2tf(p3));
            *(uint2*)&Ps[rowA * PSTR + nt * 8 + 2 * tg] = uA;
            *(uint2*)&Ps[rowB * PSTR + nt * 8 + 2 * tg] = uB;
        }
#pragma unroll
        for (int off = 1; off < 4; off <<= 1) {
            rsA += __shfl_xor_sync(0xffffffffu, rsA, off);
            rsB += __shfl_xor_sync(0xffffffffu, rsB, off);
        }
        lA = lA * scaA + rsA;
        lB = lB * scaB + rsB;
#pragma unroll
        for (int nt = 0; nt < 16; nt++) {
            acc[nt][0] *= scaA; acc[nt][1] *= scaA;
            acc[nt][2] *= scaB; acc[nt][3] *= scaB;
        }
        __syncwarp();

        // ---- O += P V (tf32) ----
#pragma unroll
        for (int kv = 0; kv < 64; kv += 8) {
            unsigned a0 = Ps[rowA * PSTR + kv + tg];
            unsigned a1 = Ps[rowB * PSTR + kv + tg];
            unsigned a2 = Ps[rowA * PSTR + kv + tg + 4];
            unsigned a3 = Ps[rowB * PSTR + kv + tg + 4];
#pragma unroll
            for (int nt = 0; nt < 16; nt++) {
                const int n = nt * 8 + g;
                unsigned b0 = Vs[(kv + tg) * VSTR + n];
                unsigned b1 = Vs[(kv + tg + 4) * VSTR + n];
                mma_tf32(acc[nt], a0, a1, a2, a3, b0, b1);
            }
        }
        __syncwarp();
    }

    // epilogue: write fp16 Y (feeds fp16 Wo GEMM directly)
    const float invA = 1.f / lA;
    const float invB = 1.f / lB;
#pragma unroll
    for (int nt = 0; nt < 16; nt++) {
        const int col = nt * 8 + 2 * tg;
        size_t oA = ((size_t)(b * PT + q0 + rowA) * PH + h) * PD + col;
        size_t oB = ((size_t)(b * PT + q0 + rowB) * PH + h) * PD + col;
        __half2 hA = __floats2half2_rn(acc[nt][0] * invA, acc[nt][1] * invA);
        __half2 hB = __floats2half2_rn(acc[nt][2] * invB, acc[nt][3] * invB);
        *(unsigned*)&Yh[oA] = *(unsigned*)&hA;
        *(unsigned*)&Yh[oB] = *(unsigned*)&hB;
    }
}

// ---------------- launch ----------------
extern "C" void kernel_launch(void* const* d_in, const int* in_sizes, int n_in,
                              void* d_out, int out_size)
{
    const float* x   = (const float*)d_in[0];
    const float* cosp= (const float*)d_in[1];
    const float* sinp= (const float*)d_in[2];
    const float* Wq  = (const float*)d_in[3];
    const float* Wk  = (const float*)d_in[4];
    const float* Wv  = (const float*)d_in[5];
    const float* Wo  = (const float*)d_in[6];
    const float* fw  = (const float*)d_in[7];
    const float* fb  = (const float*)d_in[8];
    const float* wl  = (const float*)d_in[9];
    const int*   win = (const int*)d_in[10];
    float* out = (float*)d_out;

    float *q, *k, *v, *lf, *cf;
    __half *qh, *kh, *xh, *yh, *wqh, *wkh, *wvh, *woh;
    cudaGetSymbolAddress((void**)&q, g_q);
    cudaGetSymbolAddress((void**)&k, g_k);
    cudaGetSymbolAddress((void**)&v, g_v);
    cudaGetSymbolAddress((void**)&lf, g_lf);
    cudaGetSymbolAddress((void**)&cf, g_cf);
    cudaGetSymbolAddress((void**)&qh, g_qh);
    cudaGetSymbolAddress((void**)&kh, g_kh);
    cudaGetSymbolAddress((void**)&xh, g_xh);
    cudaGetSymbolAddress((void**)&yh, g_yh);
    cudaGetSymbolAddress((void**)&wqh, g_wqh);
    cudaGetSymbolAddress((void**)&wkh, g_wkh);
    cudaGetSymbolAddress((void**)&wvh, g_wvh);
    cudaGetSymbolAddress((void**)&woh, g_woh);

    cudaFuncSetAttribute(hgemm, cudaFuncAttributeMaxDynamicSharedMemorySize, HG_SMEM);
    cudaFuncSetAttribute(hgemm_qkv, cudaFuncAttributeMaxDynamicSharedMemorySize, HG_SMEM);
    cudaFuncSetAttribute(attn_mma_kernel, cudaFuncAttributeMaxDynamicSharedMemorySize, AT_SMEM);

    // 0: x -> fp16
    f2h_conv<<<(PM * PC / 4 + 255) / 256, 256>>>(x, xh, PM * PC / 4);
    // 1: weights -> transposed [N,K] fp16
    dim3 wt(64, 64, 4);
    wtrans_h<<<wt, 256>>>(Wq, Wk, Wv, Wo, wqh, wkh, wvh, woh);
    // 2,3: gates
    gate_kernel<<<PM / 4, 256>>>(x, fw, fb, wl, lf);
    cumsum_kernel<<<PB * PH, 256>>>(lf, cf);
    // 4: QKV GEMM (fp16 tensor cores)
    dim3 gq(PHD / 128, PM / 128, 3);              // (16, 32, 3)
    hgemm_qkv<<<gq, 256, HG_SMEM>>>(xh, wqh, wkh, wvh, q, k, v, PM, PHD, PC);
    // 5,6: rope+rms -> fp16 (q pre-scaled by 1/sqrt(D))
    rope_rms_h<<<(PB * PT * PH) / 8, 256>>>(q, qh, cosp, sinp, 0.08838834764831845f);
    rope_rms_h<<<(PB * PT * PH) / 8, 256>>>(k, kh, cosp, sinp, 1.0f);
    // 7: attention (fp16 QK^T, tf32 PV), writes fp16 Y
    dim3 ag(PT / 128, PH, PB);                    // (16, 16, 2)
    attn_mma_kernel<<<ag, 256, AT_SMEM>>>(qh, kh, v, cf, yh, win);
    // 8: Wo GEMM (fp16)
    dim3 gg(PC / 128, PM / 128);                  // (16, 32)
    hgemm<<<gg, 256, HG_SMEM>>>(yh, woh, out, PM, PC, PC);
}

// round 11
// speedup vs baseline: 3.0317x; 1.2168x over previous
#include <cuda_runtime.h>
#include <cuda_bf16.h>
#include <cuda_fp16.h>
#include <math.h>
#include <cstdint>

// Problem constants (fixed by setup_inputs)
#define PB 2
#define PT 2048
#define PC 2048
#define PH 16
#define PD 128
#define PM (PB*PT)        // 4096 rows of x
#define PHD (PH*PD)       // 2048

// ---------------- scratch (device globals; no allocs allowed) ----------------
__device__ float g_q[PB*PT*PH*PD];
__device__ float g_k[PB*PT*PH*PD];
__device__ float g_lf[PB*PH*PT];
__device__ float g_cf[PB*PH*PT];
__device__ __half g_vh[PB*PT*PH*PD]; // V, fp16 (written by QKV GEMM)
__device__ __half g_qh[PB*PT*PH*PD]; // rope+rms output, fp16, q pre-scaled
__device__ __half g_kh[PB*PT*PH*PD];
__device__ __half g_xh[PM*PC];       // x, fp16
__device__ __half g_yh[PM*PHD];      // attention output, fp16
__device__ __half g_wqh[PC*PHD];     // Wq^T [N,K], fp16
__device__ __half g_wkh[PC*PHD];
__device__ __half g_wvh[PC*PHD];
__device__ __half g_woh[PC*PC];

__device__ __forceinline__ void cp16s(unsigned saddr, const void* g) {
    asm volatile("cp.async.cg.shared.global [%0], [%1], 16;" :: "r"(saddr), "l"(g));
}

__device__ __forceinline__ void mma_f16(float* c, unsigned a0, unsigned a1,
                                        unsigned a2, unsigned a3,
                                        unsigned b0, unsigned b1) {
    asm volatile(
        "mma.sync.aligned.m16n8k16.row.col.f32.f16.f16.f32 "
        "{%0,%1,%2,%3}, {%4,%5,%6,%7}, {%8,%9}, {%0,%1,%2,%3};"
        : "+f"(c[0]), "+f"(c[1]), "+f"(c[2]), "+f"(c[3])
        : "r"(a0), "r"(a1), "r"(a2), "r"(a3), "r"(b0), "r"(b1));
}

__device__ __forceinline__ void ldsm_x4(unsigned& r0, unsigned& r1,
                                        unsigned& r2, unsigned& r3, unsigned sa) {
    asm volatile("ldmatrix.sync.aligned.m8n8.x4.shared.b16 {%0,%1,%2,%3}, [%4];"
                 : "=r"(r0), "=r"(r1), "=r"(r2), "=r"(r3) : "r"(sa));
}

__device__ __forceinline__ void ldsm_x4t(unsigned& r0, unsigned& r1,
                                         unsigned& r2, unsigned& r3, unsigned sa) {
    asm volatile("ldmatrix.sync.aligned.m8n8.x4.trans.shared.b16 {%0,%1,%2,%3}, [%4];"
                 : "=r"(r0), "=r"(r1), "=r"(r2), "=r"(r3) : "r"(sa));
}

// ================= fp16 tensor-core GEMM: C = A[M,K] @ Bt[N,K]^T =============
#define HS 72                           // smem row stride in halfs (144 bytes)
#define HTILE (128*HS*2)                // 18432 B per operand tile
#define HSTAGE (2*HTILE)                // 36864
#define HG_SMEM (3*HSTAGE)              // 110592

__device__ __forceinline__ void hgemm_body(const __half* __restrict__ A,
                                           const __half* __restrict__ Bt,
                                           float* __restrict__ Cf,
                                           __half* __restrict__ Ch,
                                           int M, int N, int K)
{
    extern __shared__ char smem[];
    unsigned sbase;
    asm("{ .reg .u64 t; cvta.to.shared.u64 t, %1; cvt.u32.u64 %0, t; }"
        : "=r"(sbase) : "l"(smem));

    const int tid = threadIdx.x;
    const int lane = tid & 31, warp = tid >> 5;
    const int g = lane >> 2, tg = lane & 3;
    const int wm = (warp & 3) * 32;
    const int wn = (warp >> 2) * 64;
    const int bm = blockIdx.y * 128, bn = blockIdx.x * 128;

    const unsigned aoff = (unsigned)(wm + (lane & 15)) * 144 + ((lane >> 4) << 4);
    const unsigned boff = (unsigned)(wn + (lane & 7) + ((lane >> 4) << 3)) * 144
                        + (((lane >> 3) & 1) << 4);

    float acc[2][8][4];
#pragma unroll
    for (int mt = 0; mt < 2; mt++)
#pragma unroll
        for (int nt = 0; nt < 8; nt++)
#pragma unroll
            for (int i = 0; i < 4; i++) acc[mt][nt][i] = 0.f;

    const int r0 = tid >> 3, cc = tid & 7;
    const __half* Ag = A + (size_t)(bm + r0) * K + cc * 8;
    const __half* Bg = Bt + (size_t)(bn + r0) * K + cc * 8;
    const int nT = K / 64;

#define HLOAD(T, S)                                                             \
    {                                                                           \
        unsigned sa = sbase + (S) * HSTAGE + r0 * 144 + cc * 16;                \
        const __half* ga = Ag + (size_t)(T) * 64;                               \
        const __half* gb = Bg + (size_t)(T) * 64;                               \
        _Pragma("unroll")                                                       \
        for (int i = 0; i < 4; i++) {                                           \
            cp16s(sa + i * (32 * 144),         ga + (size_t)(32 * i) * K);      \
            cp16s(sa + HTILE + i * (32 * 144), gb + (size_t)(32 * i) * K);      \
        }                                                                       \
        asm volatile("cp.async.commit_group;");                                 \
    }

    HLOAD(0, 0);
    HLOAD(1, 1);

    int sid = 0, sid2 = 2;
    for (int t = 0; t < nT; t++) {
        if (t + 1 < nT) asm volatile("cp.async.wait_group 1;");
        else            asm volatile("cp.async.wait_group 0;");
        __syncthreads();
        if (t + 2 < nT) HLOAD(t + 2, sid2);

        const unsigned As = sbase + sid * HSTAGE;
        const unsigned Bs = As + HTILE;

#pragma unroll
        for (int kk = 0; kk < 4; kk++) {
            const unsigned kkb = kk << 5;
            unsigned a[2][4];
            ldsm_x4(a[0][0], a[0][1], a[0][2], a[0][3], As + aoff + kkb);
            ldsm_x4(a[1][0], a[1][1], a[1][2], a[1][3], As + aoff + 16 * 144 + kkb);
#pragma unroll
            for (int ntp = 0; ntp < 4; ntp++) {
                unsigned b0, b1, b2, b3;
                ldsm_x4(b0, b1, b2, b3, Bs + boff + ntp * (16 * 144) + kkb);
#pragma unroll
                for (int mt = 0; mt < 2; mt++) {
                    mma_f16(acc[mt][2 * ntp],     a[mt][0], a[mt][1], a[mt][2], a[mt][3], b0, b1);
                    mma_f16(acc[mt][2 * ntp + 1], a[mt][0], a[mt][1], a[mt][2], a[mt][3], b2, b3);
                }
            }
        }
        sid = (sid == 2) ? 0 : sid + 1;
        sid2 = (sid2 == 2) ? 0 : sid2 + 1;
    }
#undef HLOAD

    if (Ch) {
#pragma unroll
        for (int mt = 0; mt < 2; mt++)
#pragma unroll
            for (int nt = 0; nt < 8; nt++) {
                const int row0 = bm + wm + mt * 16 + g;
                const int col = bn + wn + nt * 8 + 2 * tg;
                __half2 h0 = __floats2half2_rn(acc[mt][nt][0], acc[mt][nt][1]);
                __half2 h1 = __floats2half2_rn(acc[mt][nt][2], acc[mt][nt][3]);
                *(unsigned*)&Ch[(size_t)row0 * N + col] = *(unsigned*)&h0;
                *(unsigned*)&Ch[(size_t)(row0 + 8) * N + col] = *(unsigned*)&h1;
            }
    } else {
#pragma unroll
        for (int mt = 0; mt < 2; mt++)
#pragma unroll
            for (int nt = 0; nt < 8; nt++) {
                const int row0 = bm + wm + mt * 16 + g;
                const int col = bn + wn + nt * 8 + 2 * tg;
                *(float2*)&Cf[(size_t)row0 * N + col] =
                    make_float2(acc[mt][nt][0], acc[mt][nt][1]);
                *(float2*)&Cf[(size_t)(row0 + 8) * N + col] =
                    make_float2(acc[mt][nt][2], acc[mt][nt][3]);
            }
    }
}

__global__ __launch_bounds__(256, 2) void hgemm(const __half* __restrict__ A,
                                                const __half* __restrict__ Bt,
                                                float* __restrict__ C,
                                                int M, int N, int K)
{
    hgemm_body(A, Bt, C, (__half*)0, M, N, K);
}

__global__ __launch_bounds__(256, 2) void hgemm_qkv(const __half* __restrict__ A,
                                                    const __half* __restrict__ B0,
                                                    const __half* __restrict__ B1,
                                                    const __half* __restrict__ B2,
                                                    float* __restrict__ C0,
                                                    float* __restrict__ C1,
                                                    __half* __restrict__ C2h,
                                                    int M, int N, int K)
{
    if (blockIdx.z == 0)      hgemm_body(A, B0, C0, (__half*)0, M, N, K);
    else if (blockIdx.z == 1) hgemm_body(A, B1, C1, (__half*)0, M, N, K);
    else                      hgemm_body(A, B2, (float*)0, C2h, M, N, K);
}

// ---------------- fp32 -> fp16 elementwise ----------------
__global__ __launch_bounds__(256) void f2h_conv(const float* __restrict__ in,
                                                __half* __restrict__ out, int n4)
{
    int i = blockIdx.x * 256 + threadIdx.x;
    if (i < n4) {
        float4 v = ((const float4*)in)[i];
        __half2 h0 = __floats2half2_rn(v.x, v.y);
        __half2 h1 = __floats2half2_rn(v.z, v.w);
        *(uint2*)&out[i * 4] = make_uint2(*(unsigned*)&h0, *(unsigned*)&h1);
    }
}

// ---------------- weight transpose + fp16: D[n][k] = h(W[k][n]) ----------------
__global__ __launch_bounds__(256) void wtrans_h(const float* __restrict__ s0,
                                                const float* __restrict__ s1,
                                                const float* __restrict__ s2,
                                                const float* __restrict__ s3,
                                                __half* __restrict__ d0,
                                                __half* __restrict__ d1,
                                                __half* __restrict__ d2,
                                                __half* __restrict__ d3)
{
    const int z = blockIdx.z;
    const float* S = (z == 0) ? s0 : (z == 1) ? s1 : (z == 2) ? s2 : s3;
    __half* D = (z == 0) ? d0 : (z == 1) ? d1 : (z == 2) ? d2 : d3;
    __shared__ float tile[32][33];
    const int tx = threadIdx.x & 31, ty = threadIdx.x >> 5;
    const int col = blockIdx.x * 32 + tx;
#pragma unroll
    for (int jj = 0; jj < 4; jj++)
        tile[ty + 8 * jj][tx] = S[(size_t)(blockIdx.y * 32 + ty + 8 * jj) * 2048 + col];
    __syncthreads();
    const int ocol = blockIdx.y * 32 + tx;
#pragma unroll
    for (int jj = 0; jj < 4; jj++)
        D[(size_t)(blockIdx.x * 32 + ty + 8 * jj) * 2048 + ocol] =
            __float2half_rn(tile[tx][ty + 8 * jj]);
}

// ---------------- gate kernel: 4 rows/block, float4 W loads ----------------
__global__ __launch_bounds__(256) void gate_kernel(const float* __restrict__ x,
                                                   const float* __restrict__ fw,
                                                   const float* __restrict__ fb,
                                                   const float* __restrict__ wl,
                                                   float* __restrict__ lf)
{
    __shared__ float xs[4][2048];
    __shared__ float4 red4[8][8][4];
    __shared__ float dots[4][32];
    const int bt0 = blockIdx.x * 4;
    const int tid = threadIdx.x;
    const int warp = tid >> 5, lane = tid & 31;
    const int grp = lane >> 2, koff = lane & 3;

#pragma unroll
    for (int i = 0; i < 8; i++) {
        int idx = tid + 256 * i;
        int row = idx >> 9, c4 = idx & 511;
        *(float4*)&xs[row][c4 * 4] =
            *(const float4*)&x[(size_t)(bt0 + row) * PC + c4 * 4];
    }
    __syncthreads();

    const float* W = (grp < 4) ? fw : wl;
    const int h4 = (grp & 3) * 4;
    float4 s[4];
#pragma unroll
    for (int r = 0; r < 4; r++) s[r] = make_float4(0.f, 0.f, 0.f, 0.f);

    for (int i = 0; i < 64; i++) {
        int c = koff + 4 * warp + 32 * i;
        float4 wv = *(const float4*)&W[c * PH + h4];
#pragma unroll
        for (int r = 0; r < 4; r++) {
            float xv = xs[r][c];
            s[r].x += xv * wv.x; s[r].y += xv * wv.y;
            s[r].z += xv * wv.z; s[r].w += xv * wv.w;
        }
    }
#pragma unroll
    for (int off = 1; off < 4; off <<= 1) {
#pragma unroll
        for (int r = 0; r < 4; r++) {
            s[r].x += __shfl_xor_sync(0xffffffffu, s[r].x, off);
            s[r].y += __shfl_xor_sync(0xffffffffu, s[r].y, off);
            s[r].z += __shfl_xor_sync(0xffffffffu, s[r].z, off);
            s[r].w += __shfl_xor_sync(0xffffffffu, s[r].w, off);
        }
    }
    if (koff == 0) {
#pragma unroll
        for (int r = 0; r < 4; r++) red4[warp][grp][r] = s[r];
    }
    __syncthreads();
    if (tid < 128) {
        int row = tid >> 5, o = tid & 31;
        int gg = o >> 2, comp = o & 3;
        float t = 0.f;
#pragma unroll
        for (int w2 = 0; w2 < 8; w2++)
            t += ((const float*)&red4[w2][gg][row])[comp];
        dots[row][o] = t;
    }
    __syncthreads();
    if (tid < 64) {
        const int row = tid >> 4, hh = tid & 15;
        const int bt = bt0 + row;
        const int b = bt >> 11, t = bt & (PT - 1);
        float fdot = dots[row][hh] + fb[hh];
        float ldot = dots[row][16 + hh];
        float lam = ldot > 0.f ? ldot + 1.f : expf(ldot);
        float logit = fdot * lam;
        float ls = (logit >= 0.f) ? -log1pf(expf(-logit))
                                  : (logit - log1pf(expf(logit)));
        lf[((size_t)(b * PH + hh)) * PT + t] = ls / (lam + 0.001f);
    }
}

// ---------------- cumsum over T per (b,h) ----------------
__global__ __launch_bounds__(256) void cumsum_kernel(const float* __restrict__ lf,
                                                     float* __restrict__ cf)
{
    __shared__ float tot[256];
    const int bh = blockIdx.x, tid = threadIdx.x;
    const float* in = lf + (size_t)bh * PT;
    float* out = cf + (size_t)bh * PT;
    float v[8];
    float r = 0.f;
#pragma unroll
    for (int jj = 0; jj < 8; jj++) { r += in[tid * 8 + jj]; v[jj] = r; }
    tot[tid] = r;
    __syncthreads();
    for (int off = 1; off < 256; off <<= 1) {
        float t = 0.f;
        if (tid >= off) t = tot[tid - off];
        __syncthreads();
        if (tid >= off) tot[tid] += t;
        __syncthreads();
    }
    float base = tid ? tot[tid - 1] : 0.f;
#pragma unroll
    for (int jj = 0; jj < 8; jj++) out[tid * 8 + jj] = v[jj] + base;
}

// ---------- RoPE + RMSNorm: fp32 in, fp16 out (optionally pre-scaled) --------
__global__ __launch_bounds__(256) void rope_rms_h(const float* __restrict__ in,
                                                  __half* __restrict__ outh,
                                                  const float* __restrict__ cosp,
                                                  const float* __restrict__ sinp,
                                                  float scale)
{
    const int wid = blockIdx.x * 8 + (threadIdx.x >> 5);
    const int lane = threadIdx.x & 31;
    const int t = (wid >> 4) & (PT - 1);
    const float* row = in + (size_t)wid * PD;
    __half* orow = outh + (size_t)wid * PD;
    const int i0 = lane, i1 = lane + 32;
    float x1a = row[i0], x1b = row[i1];
    float x2a = row[i0 + 64], x2b = row[i1 + 64];
    float ca = cosp[t * 64 + i0], cb = cosp[t * 64 + i1];
    float sa = sinp[t * 64 + i0], sb = sinp[t * 64 + i1];
    float o0 = x1a * ca + x2a * sa;
    float o1 = x1b * cb + x2b * sb;
    float o2 = x2a * ca - x1a * sa;
    float o3 = x2b * cb - x1b * sb;
    float ss = o0 * o0 + o1 * o1 + o2 * o2 + o3 * o3;
#pragma unroll
    for (int off = 16; off > 0; off >>= 1) ss += __shfl_xor_sync(0xffffffffu, ss, off);
    float vv = ss * (1.f / 128.f) + 1.1920929e-07f;
    float inv = rsqrtf(vv);
    inv = inv * (1.5f - 0.5f * vv * inv * inv);
    inv *= scale;
    orow[i0] = __float2half_rn(o0 * inv);
    orow[i1] = __float2half_rn(o1 * inv);
    orow[i0 + 64] = __float2half_rn(o2 * inv);
    orow[i1 + 64] = __float2half_rn(o3 * inv);
}

// ------------- windowed gated attention: all-fp16 mma, P in registers --------
#define SQ_OFF 0
#define SK_OFF 34816
#define SV_OFF 52224
#define SC_OFF 69632
#define AT_SMEM 69888

__global__ __launch_bounds__(256) void attn_mma_kernel(const __half* __restrict__ Qh,
                                                       const __half* __restrict__ Kh,
                                                       const __half* __restrict__ Vh,
                                                       const float* __restrict__ cumF,
                                                       __half* __restrict__ Yh,
                                                       const int* __restrict__ winp)
{
    extern __shared__ char sm8[];
    unsigned sb;
    asm("{ .reg .u64 t; cvta.to.shared.u64 t, %1; cvt.u32.u64 %0, t; }"
        : "=r"(sb) : "l"(sm8));
    float* cfk = (float*)(sm8 + SC_OFF);

    const int tid = threadIdx.x;
    const int lane = tid & 31, warp = tid >> 5;
    const int g = lane >> 2, tg = lane & 3;
    const int wm = warp * 16;
    const int qt = blockIdx.x, h = blockIdx.y, b = blockIdx.z;
    const int q0 = qt * 128;
    const int win = *winp;
    const float* cF = cumF + (size_t)(b * PH + h) * PT;

    const unsigned qoff = (unsigned)(wm + (lane & 15)) * 272 + ((lane >> 4) << 4);
    const unsigned koff = (unsigned)((lane & 7) + ((lane >> 4) << 3)) * 272
                        + (((lane >> 3) & 1) << 4);
    const unsigned voff = (unsigned)((lane & 7) + (((lane >> 3) & 1) << 3)) * 272
                        + ((lane >> 4) << 4);

    {
        const __half* qg = Qh + ((size_t)(b * PT + q0) * PH + h) * PD;
#pragma unroll
        for (int i = 0; i < 8; i++) {
            int idx = tid + 256 * i;
            int r = idx >> 4, c = idx & 15;
            cp16s(sb + SQ_OFF + r * 272 + c * 16, qg + (size_t)r * PHD + c * 8);
        }
        asm volatile("cp.async.commit_group;");
    }
    const int rowA = wm + g, rowB = wm + g + 8;
    const float cfqA = cF[q0 + rowA];
    const float cfqB = cF[q0 + rowB];
    const int qiA = q0 + rowA, qiB = q0 + rowB;

    float mA = -1e30f, mB = -1e30f, lA = 0.f, lB = 0.f;
    float acc[16][4];
#pragma unroll
    for (int nt = 0; nt < 16; nt++)
#pragma unroll
        for (int i = 0; i < 4; i++) acc[nt][i] = 0.f;

    const int kt_hi = (q0 + 127) >> 6;
    const int lo = q0 - win + 1;
    const int kt_min = lo > 0 ? (lo >> 6) : 0;

    for (int kt = kt_hi; kt >= kt_min; --kt) {
        const int kb = kt * 64;
        __syncthreads();
        {
            const size_t base = ((size_t)(b * PT + kb) * PH + h) * PD;
            const __half* kg = Kh + base;
            const __half* vg = Vh + base;
#pragma unroll
            for (int i = 0; i < 4; i++) {
                int idx = tid + 256 * i;
                int r = idx >> 4, c = idx & 15;
                cp16s(sb + SK_OFF + r * 272 + c * 16, kg + (size_t)r * PHD + c * 8);
                cp16s(sb + SV_OFF + r * 272 + c * 16, vg + (size_t)r * PHD + c * 8);
            }
            asm volatile("cp.async.commit_group;");
            if (tid < 64) cfk[tid] = cF[kb + tid];
        }
        asm volatile("cp.async.wait_group 0;");
        __syncthreads();

        float sc_[8][4];
#pragma unroll
        for (int nt = 0; nt < 8; nt++)
#pragma unroll
            for (int i = 0; i < 4; i++) sc_[nt][i] = 0.f;

#pragma unroll
        for (int kk = 0; kk < 8; kk++) {
            const unsigned kkb = kk << 5;
            unsigned a0, a1, a2, a3;
            ldsm_x4(a0, a1, a2, a3, sb + SQ_OFF + qoff + kkb);
#pragma unroll
            for (int ntp = 0; ntp < 4; ntp++) {
                unsigned b0, b1, b2, b3;
                ldsm_x4(b0, b1, b2, b3, sb + SK_OFF + koff + ntp * (16 * 272) + kkb);
                mma_f16(sc_[2 * ntp],     a0, a1, a2, a3, b0, b1);
                mma_f16(sc_[2 * ntp + 1], a0, a1, a2, a3, b2, b3);
            }
        }

#pragma unroll
        for (int nt = 0; nt < 8; nt++) {
            const int j0 = kb + nt * 8 + 2 * tg;
            const int j1 = j0 + 1;
            const float c0 = cfk[nt * 8 + 2 * tg];
            const float c1 = cfk[nt * 8 + 2 * tg + 1];
            sc_[nt][0] = (j0 <= qiA && qiA - j0 < win) ? sc_[nt][0] + cfqA - c0 : -1e30f;
            sc_[nt][1] = (j1 <= qiA && qiA - j1 < win) ? sc_[nt][1] + cfqA - c1 : -1e30f;
            sc_[nt][2] = (j0 <= qiB && qiB - j0 < win) ? sc_[nt][2] + cfqB - c0 : -1e30f;
            sc_[nt][3] = (j1 <= qiB && qiB - j1 < win) ? sc_[nt][3] + cfqB - c1 : -1e30f;
        }
        float mxA = -1e30f, mxB = -1e30f;
#pragma unroll
        for (int nt = 0; nt < 8; nt++) {
            mxA = fmaxf(mxA, fmaxf(sc_[nt][0], sc_[nt][1]));
            mxB = fmaxf(mxB, fmaxf(sc_[nt][2], sc_[nt][3]));
        }
#pragma unroll
        for (int off = 1; off < 4; off <<= 1) {
            mxA = fmaxf(mxA, __shfl_xor_sync(0xffffffffu, mxA, off));
            mxB = fmaxf(mxB, __shfl_xor_sync(0xffffffffu, mxB, off));
        }
        const float mnA = fmaxf(mA, mxA);
        const float mnB = fmaxf(mB, mxB);
        const float scaA = __expf(mA - mnA);
        const float scaB = __expf(mB - mnB);
        mA = mnA; mB = mnB;

        float rsA = 0.f, rsB = 0.f;
        unsigned paA[8], paB[8];
#pragma unroll
        for (int nt = 0; nt < 8; nt++) {
            float p0 = (sc_[nt][0] > -1e29f) ? __expf(sc_[nt][0] - mnA) : 0.f;
            float p1 = (sc_[nt][1] > -1e29f) ? __expf(sc_[nt][1] - mnA) : 0.f;
            float p2 = (sc_[nt][2] > -1e29f) ? __expf(sc_[nt][2] - mnB) : 0.f;
            float p3 = (sc_[nt][3] > -1e29f) ? __expf(sc_[nt][3] - mnB) : 0.f;
            rsA += p0 + p1;
            rsB += p2 + p3;
            __half2 hA = __floats2half2_rn(p0, p1);
            __half2 hB = __floats2half2_rn(p2, p3);
            paA[nt] = *(unsigned*)&hA;
            paB[nt] = *(unsigned*)&hB;
        }
#pragma unroll
        for (int off = 1; off < 4; off <<= 1) {
            rsA += __shfl_xor_sync(0xffffffffu, rsA, off);
            rsB += __shfl_xor_sync(0xffffffffu, rsB, off);
        }
        lA = lA * scaA + rsA;
        lB = lB * scaB + rsB;
#pragma unroll
        for (int nt = 0; nt < 16; nt++) {
            acc[nt][0] *= scaA; acc[nt][1] *= scaA;
            acc[nt][2] *= scaB; acc[nt][3] *= scaB;
        }

#pragma unroll
        for (int j = 0; j < 4; j++) {
            const unsigned a0 = paA[2 * j], a1 = paB[2 * j];
            const unsigned a2 = paA[2 * j + 1], a3 = paB[2 * j + 1];
            const unsigned vrow = sb + SV_OFF + voff + j * (16 * 272);
#pragma unroll
            for (int ntp = 0; ntp < 8; ntp++) {
                unsigned b0, b1, b2, b3;
                ldsm_x4t(b0, b1, b2, b3, vrow + ntp * 32);
                mma_f16(acc[2 * ntp],     a0, a1, a2, a3, b0, b1);
                mma_f16(acc[2 * ntp + 1], a0, a1, a2, a3, b2, b3);
            }
        }
    }

    const float invA = 1.f / lA;
    const float invB = 1.f / lB;
#pragma unroll
    for (int nt = 0; nt < 16; nt++) {
        const int col = nt * 8 + 2 * tg;
        size_t oA = ((size_t)(b * PT + q0 + rowA) * PH + h) * PD + col;
        size_t oB = ((size_t)(b * PT + q0 + rowB) * PH + h) * PD + col;
        __half2 hA = __floats2half2_rn(acc[nt][0] * invA, acc[nt][1] * invA);
        __half2 hB = __floats2half2_rn(acc[nt][2] * invB, acc[nt][3] * invB);
        *(unsigned*)&Yh[oA] = *(unsigned*)&hA;
        *(unsigned*)&Yh[oB] = *(unsigned*)&hB;
    }
}

// ---------------- launch ----------------
extern "C" void kernel_launch(void* const* d_in, const int* in_sizes, int n_in,
                              void* d_out, int out_size)
{
    const float* x   = (const float*)d_in[0];
    const float* cosp= (const float*)d_in[1];
    const float* sinp= (const float*)d_in[2];
    const float* Wq  = (const float*)d_in[3];
    const float* Wk  = (const float*)d_in[4];
    const float* Wv  = (const float*)d_in[5];
    const float* Wo  = (const float*)d_in[6];
    const float* fw  = (const float*)d_in[7];
    const float* fb  = (const float*)d_in[8];
    const float* wl  = (const float*)d_in[9];
    const int*   win = (const int*)d_in[10];
    float* out = (float*)d_out;

    float *q, *k, *lf, *cf;
    __half *vh, *qh, *kh, *xh, *yh, *wqh, *wkh, *wvh, *woh;
    cudaGetSymbolAddress((void**)&q, g_q);
    cudaGetSymbolAddress((void**)&k, g_k);
    cudaGetSymbolAddress((void**)&lf, g_lf);
    cudaGetSymbolAddress((void**)&cf, g_cf);
    cudaGetSymbolAddress((void**)&vh, g_vh);
    cudaGetSymbolAddress((void**)&qh, g_qh);
    cudaGetSymbolAddress((void**)&kh, g_kh);
    cudaGetSymbolAddress((void**)&xh, g_xh);
    cudaGetSymbolAddress((void**)&yh, g_yh);
    cudaGetSymbolAddress((void**)&wqh, g_wqh);
    cudaGetSymbolAddress((void**)&wkh, g_wkh);
    cudaGetSymbolAddress((void**)&wvh, g_wvh);
    cudaGetSymbolAddress((void**)&woh, g_woh);

    cudaFuncSetAttribute(hgemm, cudaFuncAttributeMaxDynamicSharedMemorySize, HG_SMEM);
    cudaFuncSetAttribute(hgemm_qkv, cudaFuncAttributeMaxDynamicSharedMemorySize, HG_SMEM);
    cudaFuncSetAttribute(attn_mma_kernel, cudaFuncAttributeMaxDynamicSharedMemorySize, AT_SMEM);

    f2h_conv<<<(PM * PC / 4 + 255) / 256, 256>>>(x, xh, PM * PC / 4);
    dim3 wt(64, 64, 4);
    wtrans_h<<<wt, 256>>>(Wq, Wk, Wv, Wo, wqh, wkh, wvh, woh);
    gate_kernel<<<PM / 4, 256>>>(x, fw, fb, wl, lf);
    cumsum_kernel<<<PB * PH, 256>>>(lf, cf);
    dim3 gq(PHD / 128, PM / 128, 3);              // (16, 32, 3)
    hgemm_qkv<<<gq, 256, HG_SMEM>>>(xh, wqh, wkh, wvh, q, k, vh, PM, PHD, PC);
    rope_rms_h<<<(PB * PT * PH) / 8, 256>>>(q, qh, cosp, sinp, 0.08838834764831845f);
    rope_rms_h<<<(PB * PT * PH) / 8, 256>>>(k, kh, cosp, sinp, 1.0f);
    dim3 ag(PT / 128, PH, PB);                    // (16, 16, 2)
    attn_mma_kernel<<<ag, 256, AT_SMEM>>>(qh, kh, vh, cf, yh, win);
    dim3 gg(PC / 128, PM / 128);                  // (16, 32)
    hgemm<<<gg, 256, HG_SMEM>>>(yh, woh, out, PM, PC, PC);
}